// round 1
// baseline (speedup 1.0000x reference)
#include <cuda_runtime.h>
#include <cstdint>

#define NB    2048
#define ND    40960
#define NBASE 288
#define NH    576     // 2*NBASE
#define NA0   144
#define NMOVE 4096
#define KTOT  720     // NA0 + NH

// -------- device scratch (no allocations allowed) --------
__device__ float g_WTw[(size_t)ND * NBASE];   // W_w^T  [D, 288]
__device__ float g_WTb[(size_t)ND * NBASE];   // W_b^T  [D, 288]
__device__ float g_WTv0[NH * 32];             // W_v0^T [576, 32]
__device__ float g_base[(size_t)NB * NH];     // relu'd base [B, 576]
__device__ float g_a0[(size_t)NB * NA0];      // relu'd a0   [B, 144]

// ---------------- transpose: in[R,C] -> out[C,R] ----------------
__global__ void transpose_kernel(const float* __restrict__ in, int R, int C, int which) {
    float* out = (which == 0) ? g_WTw : (which == 1) ? g_WTb : g_WTv0;
    __shared__ float tile[32][33];
    int c0 = blockIdx.x * 32;
    int r0 = blockIdx.y * 32;
    int x = threadIdx.x;
    #pragma unroll
    for (int yy = threadIdx.y; yy < 32; yy += 8) {
        int r = r0 + yy, c = c0 + x;
        tile[yy][x] = (r < R && c < C) ? in[(size_t)r * C + c] : 0.0f;
    }
    __syncthreads();
    #pragma unroll
    for (int yy = threadIdx.y; yy < 32; yy += 8) {
        int c = c0 + yy, r = r0 + x;
        if (r < R && c < C) out[(size_t)c * R + r] = tile[x][yy];
    }
}

// ---------------- feature transform + base ----------------
// One block per batch row. Threads [0,288): white, [288,576): black.
// Phase 1: cooperative scan of the dense 40960-wide mask for nonzeros.
// Phase 2: coalesced gather-sum of transposed weight rows.
#define MAXNZ 1024
__global__ __launch_bounds__(2 * NBASE) void feature_kernel(
    const float* __restrict__ pov,
    const float* __restrict__ white,
    const float* __restrict__ black,
    const float* __restrict__ b_w,
    const float* __restrict__ b_b)
{
    __shared__ int   s_idx[2][MAXNZ];
    __shared__ float s_val[2][MAXNZ];
    __shared__ int   s_cnt[2];
    int b = blockIdx.x;
    int t = threadIdx.x;
    int h = t / NBASE;            // 0 = white, 1 = black
    int i = t - h * NBASE;
    if (t < 2) s_cnt[t] = 0;
    __syncthreads();

    const float* src = h ? black : white;
    const float4* row = reinterpret_cast<const float4*>(src + (size_t)b * ND);
    for (int u = i; u < ND / 4; u += NBASE) {
        float4 v = row[u];
        if (v.x != 0.0f) { int p = atomicAdd(&s_cnt[h], 1); if (p < MAXNZ) { s_idx[h][p] = 4*u+0; s_val[h][p] = v.x; } }
        if (v.y != 0.0f) { int p = atomicAdd(&s_cnt[h], 1); if (p < MAXNZ) { s_idx[h][p] = 4*u+1; s_val[h][p] = v.y; } }
        if (v.z != 0.0f) { int p = atomicAdd(&s_cnt[h], 1); if (p < MAXNZ) { s_idx[h][p] = 4*u+2; s_val[h][p] = v.z; } }
        if (v.w != 0.0f) { int p = atomicAdd(&s_cnt[h], 1); if (p < MAXNZ) { s_idx[h][p] = 4*u+3; s_val[h][p] = v.w; } }
    }
    __syncthreads();

    const float* WT = h ? g_WTb : g_WTw;
    float acc = h ? b_b[i] : b_w[i];
    int n = s_cnt[h];
    if (n > MAXNZ) n = MAXNZ;
    int k = 0;
    for (; k + 4 <= n; k += 4) {
        float p0 = s_val[h][k+0] * WT[(size_t)s_idx[h][k+0] * NBASE + i];
        float p1 = s_val[h][k+1] * WT[(size_t)s_idx[h][k+1] * NBASE + i];
        float p2 = s_val[h][k+2] * WT[(size_t)s_idx[h][k+2] * NBASE + i];
        float p3 = s_val[h][k+3] * WT[(size_t)s_idx[h][k+3] * NBASE + i];
        acc += (p0 + p1) + (p2 + p3);
    }
    for (; k < n; k++)
        acc += s_val[h][k] * WT[(size_t)s_idx[h][k] * NBASE + i];

    float pv = pov[b];               // exactly 0.0 or 1.0
    int pos;
    if (h == 0) pos = (pv > 0.5f) ? i : (NBASE + i);
    else        pos = (pv > 0.5f) ? (NBASE + i) : i;
    g_base[(size_t)b * NH + pos] = fmaxf(acc, 0.0f);
}

// ---------------- a0 = relu(base @ W_a0^T + b_a0) ----------------
// M=2048, N=144, K=576. BM=64, BN=48, BK=16, 256 threads, 4x3 microtile.
__global__ __launch_bounds__(256) void a0_kernel(const float* __restrict__ W_a0,
                                                 const float* __restrict__ b_a0)
{
    __shared__ float sA[16][64];
    __shared__ float sB[16][48];
    int m0 = blockIdx.x * 64;
    int n0 = blockIdx.y * 48;
    int t  = threadIdx.x;
    int tx = t % 16, ty = t / 16;
    float acc[4][3] = {};
    int am = t >> 2, ak = (t & 3) * 4;

    for (int kt = 0; kt < NH; kt += 16) {
        float4 av = *reinterpret_cast<const float4*>(&g_base[(size_t)(m0 + am) * NH + kt + ak]);
        float4 bv = make_float4(0.f, 0.f, 0.f, 0.f);
        if (t < 192) bv = *reinterpret_cast<const float4*>(&W_a0[(size_t)(n0 + am) * NH + kt + ak]);
        __syncthreads();
        sA[ak+0][am] = av.x; sA[ak+1][am] = av.y; sA[ak+2][am] = av.z; sA[ak+3][am] = av.w;
        if (t < 192) { sB[ak+0][am] = bv.x; sB[ak+1][am] = bv.y; sB[ak+2][am] = bv.z; sB[ak+3][am] = bv.w; }
        __syncthreads();
        #pragma unroll
        for (int k = 0; k < 16; k++) {
            float a[4], bb[3];
            #pragma unroll
            for (int ii = 0; ii < 4; ii++) a[ii] = sA[k][ty*4 + ii];
            #pragma unroll
            for (int j = 0; j < 3; j++)  bb[j] = sB[k][tx*3 + j];
            #pragma unroll
            for (int ii = 0; ii < 4; ii++)
                #pragma unroll
                for (int j = 0; j < 3; j++)
                    acc[ii][j] += a[ii] * bb[j];
        }
    }
    #pragma unroll
    for (int ii = 0; ii < 4; ii++) {
        int m = m0 + ty*4 + ii;
        #pragma unroll
        for (int j = 0; j < 3; j++) {
            int n = n0 + tx*3 + j;
            g_a0[(size_t)m * NA0 + n] = fmaxf(acc[ii][j] + b_a0[n], 0.0f);
        }
    }
}

// ---------------- value head ----------------
// 8 rows per block, one warp per row. W_v0 used transposed (g_WTv0).
__global__ __launch_bounds__(256) void value_kernel(
    const float* __restrict__ b_v0,
    const float* __restrict__ W_v1, const float* __restrict__ b_v1,
    const float* __restrict__ W_v2, const float* __restrict__ b_v2,
    const float* __restrict__ W_vs, const float* __restrict__ b_vs,
    float* __restrict__ out)
{
    __shared__ float sbase[8][NH];
    __shared__ float sv0[8][32];
    int t  = threadIdx.x;
    int r0 = blockIdx.x * 8;
    for (int idx = t; idx < 8 * NH; idx += 256)
        sbase[idx / NH][idx % NH] = g_base[(size_t)(r0 + idx / NH) * NH + (idx % NH)];
    __syncthreads();

    int w = t / 32, lane = t % 32;
    const float* bp = sbase[w];

    // v0 = relu(W_v0 @ base + b_v0) : lane -> output o, coalesced via transposed weights
    float acc = b_v0[lane];
    const float* wp = g_WTv0 + lane;
    #pragma unroll 8
    for (int k = 0; k < NH; k++) acc += wp[(size_t)k * 32] * bp[k];
    sv0[w][lane] = fmaxf(acc, 0.0f);
    __syncwarp();

    // v1 = relu(W_v1 @ v0 + b_v1)
    float acc1 = b_v1[lane];
    #pragma unroll
    for (int j = 0; j < 32; j++) acc1 += W_v1[lane * 32 + j] * sv0[w][j];
    acc1 = fmaxf(acc1, 0.0f);

    // val = W_v2 . v1 + b_v2 + W_vs . base + b_vs
    float part = W_v2[lane] * acc1;
    for (int k = lane; k < NH; k += 32) part += W_vs[k] * bp[k];
    #pragma unroll
    for (int off = 16; off > 0; off >>= 1)
        part += __shfl_down_sync(0xffffffffu, part, off);
    if (lane == 0) out[r0 + w] = part + b_v2[0] + b_vs[0];
}

// ---------------- action head: fused K=720 GEMM ----------------
// act[m,n] = sum_{k<144} a0[m,k]*W_a1[n,k] + sum_{k<576} base[m,k]*W_as[n,k]
//            + b_a1[n] + b_as[n]
// BM=BN=128, BK=16, 256 threads, 8x8 microtile (2x2 groups of 4).
__global__ __launch_bounds__(256, 2) void act_kernel(
    const float* __restrict__ W_a1, const float* __restrict__ b_a1,
    const float* __restrict__ W_as, const float* __restrict__ b_as,
    float* __restrict__ out)
{
    __shared__ float sA[16][128];
    __shared__ float sB[16][128];
    int n0 = blockIdx.x * 128;
    int m0 = blockIdx.y * 128;
    int t  = threadIdx.x;
    int tx = t % 16, ty = t / 16;
    float acc[8][8] = {};
    int lr = t >> 1;          // row within tile, 0..127
    int lk = (t & 1) * 8;     // 0 or 8

    for (int kt = 0; kt < KTOT / 16; kt++) {
        int kbase = kt * 16;
        float4 a0v, a1v, b0v, b1v;
        if (kbase < NA0) {   // a0 segment (tiles 0..8, 144 = 9*16)
            const float* ap = &g_a0[(size_t)(m0 + lr) * NA0 + kbase + lk];
            const float* wp = &W_a1[(size_t)(n0 + lr) * NA0 + kbase + lk];
            a0v = *(const float4*)(ap);     a1v = *(const float4*)(ap + 4);
            b0v = *(const float4*)(wp);     b1v = *(const float4*)(wp + 4);
        } else {             // base segment (tiles 9..44)
            int kb = kbase - NA0;
            const float* ap = &g_base[(size_t)(m0 + lr) * NH + kb + lk];
            const float* wp = &W_as[(size_t)(n0 + lr) * NH + kb + lk];
            a0v = *(const float4*)(ap);     a1v = *(const float4*)(ap + 4);
            b0v = *(const float4*)(wp);     b1v = *(const float4*)(wp + 4);
        }
        __syncthreads();
        sA[lk+0][lr] = a0v.x; sA[lk+1][lr] = a0v.y; sA[lk+2][lr] = a0v.z; sA[lk+3][lr] = a0v.w;
        sA[lk+4][lr] = a1v.x; sA[lk+5][lr] = a1v.y; sA[lk+6][lr] = a1v.z; sA[lk+7][lr] = a1v.w;
        sB[lk+0][lr] = b0v.x; sB[lk+1][lr] = b0v.y; sB[lk+2][lr] = b0v.z; sB[lk+3][lr] = b0v.w;
        sB[lk+4][lr] = b1v.x; sB[lk+5][lr] = b1v.y; sB[lk+6][lr] = b1v.z; sB[lk+7][lr] = b1v.w;
        __syncthreads();
        #pragma unroll
        for (int k = 0; k < 16; k++) {
            float4 ta0 = *(const float4*)&sA[k][ty*4];
            float4 ta1 = *(const float4*)&sA[k][64 + ty*4];
            float4 tb0 = *(const float4*)&sB[k][tx*4];
            float4 tb1 = *(const float4*)&sB[k][64 + tx*4];
            float a[8] = {ta0.x, ta0.y, ta0.z, ta0.w, ta1.x, ta1.y, ta1.z, ta1.w};
            float bb[8] = {tb0.x, tb0.y, tb0.z, tb0.w, tb1.x, tb1.y, tb1.z, tb1.w};
            #pragma unroll
            for (int ii = 0; ii < 8; ii++)
                #pragma unroll
                for (int j = 0; j < 8; j++)
                    acc[ii][j] += a[ii] * bb[j];
        }
    }

    // epilogue: bias + store (output act region starts at offset NB)
    float bias[8];
    #pragma unroll
    for (int j = 0; j < 8; j++) {
        int n = n0 + ((j < 4) ? (tx*4 + j) : (64 + tx*4 + j - 4));
        bias[j] = b_a1[n] + b_as[n];
    }
    #pragma unroll
    for (int ii = 0; ii < 8; ii++) {
        int m = m0 + ((ii < 4) ? (ty*4 + ii) : (64 + ty*4 + ii - 4));
        float* op = out + NB + (size_t)m * NMOVE;
        float4 s0 = make_float4(acc[ii][0] + bias[0], acc[ii][1] + bias[1],
                                acc[ii][2] + bias[2], acc[ii][3] + bias[3]);
        float4 s1 = make_float4(acc[ii][4] + bias[4], acc[ii][5] + bias[5],
                                acc[ii][6] + bias[6], acc[ii][7] + bias[7]);
        *(float4*)&op[n0 + tx*4]      = s0;
        *(float4*)&op[n0 + 64 + tx*4] = s1;
    }
}

extern "C" void kernel_launch(void* const* d_in, const int* in_sizes, int n_in,
                              void* d_out, int out_size)
{
    const float* pov   = (const float*)d_in[0];
    const float* white = (const float*)d_in[1];
    const float* black = (const float*)d_in[2];
    const float* W_w   = (const float*)d_in[3];
    const float* b_w   = (const float*)d_in[4];
    const float* W_b   = (const float*)d_in[5];
    const float* b_b   = (const float*)d_in[6];
    const float* W_v0  = (const float*)d_in[7];
    const float* b_v0  = (const float*)d_in[8];
    const float* W_v1  = (const float*)d_in[9];
    const float* b_v1  = (const float*)d_in[10];
    const float* W_v2  = (const float*)d_in[11];
    const float* b_v2  = (const float*)d_in[12];
    const float* W_a0  = (const float*)d_in[13];
    const float* b_a0  = (const float*)d_in[14];
    const float* W_a1  = (const float*)d_in[15];
    const float* b_a1  = (const float*)d_in[16];
    const float* W_vs  = (const float*)d_in[17];
    const float* b_vs  = (const float*)d_in[18];
    const float* W_as  = (const float*)d_in[19];
    const float* b_as  = (const float*)d_in[20];
    float* out = (float*)d_out;

    dim3 tb(32, 8);
    transpose_kernel<<<dim3(ND / 32, NBASE / 32), tb>>>(W_w, NBASE, ND, 0);
    transpose_kernel<<<dim3(ND / 32, NBASE / 32), tb>>>(W_b, NBASE, ND, 1);
    transpose_kernel<<<dim3(NH / 32, 1), tb>>>(W_v0, 32, NH, 2);

    feature_kernel<<<NB, 2 * NBASE>>>(pov, white, black, b_w, b_b);
    a0_kernel<<<dim3(NB / 64, NA0 / 48), 256>>>(W_a0, b_a0);
    value_kernel<<<NB / 8, 256>>>(b_v0, W_v1, b_v1, W_v2, b_v2, W_vs, b_vs, out);
    act_kernel<<<dim3(NMOVE / 128, NB / 128), 256>>>(W_a1, b_a1, W_as, b_as, out);
}

// round 2
// speedup vs baseline: 1.2656x; 1.2656x over previous
#include <cuda_runtime.h>
#include <cstdint>

#define NB    2048
#define ND    40960
#define NBASE 288
#define NH    576     // 2*NBASE
#define NA0   144
#define NMOVE 4096
#define KTOT  720     // NA0 + NH

// -------- device scratch (no allocations allowed) --------
__device__ float g_WTw[(size_t)ND * NBASE];   // W_w^T  [D, 288]
__device__ float g_WTb[(size_t)ND * NBASE];   // W_b^T  [D, 288]
__device__ float g_WTv0[NH * 32];             // W_v0^T [576, 32]
__device__ float g_base[(size_t)NB * NH];     // relu'd base [B, 576]
__device__ float g_a0[(size_t)NB * NA0];      // relu'd a0   [B, 144]

// ---------------- transpose: in[R,C] -> out[C,R] ----------------
__global__ void transpose_kernel(const float* __restrict__ in, int R, int C, int which) {
    float* out = (which == 0) ? g_WTw : (which == 1) ? g_WTb : g_WTv0;
    __shared__ float tile[32][33];
    int c0 = blockIdx.x * 32;
    int r0 = blockIdx.y * 32;
    int x = threadIdx.x;
    #pragma unroll
    for (int yy = threadIdx.y; yy < 32; yy += 8) {
        int r = r0 + yy, c = c0 + x;
        tile[yy][x] = (r < R && c < C) ? in[(size_t)r * C + c] : 0.0f;
    }
    __syncthreads();
    #pragma unroll
    for (int yy = threadIdx.y; yy < 32; yy += 8) {
        int c = c0 + yy, r = r0 + x;
        if (r < R && c < C) out[(size_t)c * R + r] = tile[x][yy];
    }
}

// ---------------- feature transform + base ----------------
#define MAXNZ 1024
__global__ __launch_bounds__(2 * NBASE) void feature_kernel(
    const float* __restrict__ pov,
    const float* __restrict__ white,
    const float* __restrict__ black,
    const float* __restrict__ b_w,
    const float* __restrict__ b_b)
{
    __shared__ int   s_idx[2][MAXNZ];
    __shared__ float s_val[2][MAXNZ];
    __shared__ int   s_cnt[2];
    int b = blockIdx.x;
    int t = threadIdx.x;
    int h = t / NBASE;            // 0 = white, 1 = black
    int i = t - h * NBASE;
    if (t < 2) s_cnt[t] = 0;
    __syncthreads();

    const float* src = h ? black : white;
    const float4* row = reinterpret_cast<const float4*>(src + (size_t)b * ND);
    for (int u = i; u < ND / 4; u += NBASE) {
        float4 v = row[u];
        if (v.x != 0.0f) { int p = atomicAdd(&s_cnt[h], 1); if (p < MAXNZ) { s_idx[h][p] = 4*u+0; s_val[h][p] = v.x; } }
        if (v.y != 0.0f) { int p = atomicAdd(&s_cnt[h], 1); if (p < MAXNZ) { s_idx[h][p] = 4*u+1; s_val[h][p] = v.y; } }
        if (v.z != 0.0f) { int p = atomicAdd(&s_cnt[h], 1); if (p < MAXNZ) { s_idx[h][p] = 4*u+2; s_val[h][p] = v.z; } }
        if (v.w != 0.0f) { int p = atomicAdd(&s_cnt[h], 1); if (p < MAXNZ) { s_idx[h][p] = 4*u+3; s_val[h][p] = v.w; } }
    }
    __syncthreads();

    const float* WT = h ? g_WTb : g_WTw;
    float acc = h ? b_b[i] : b_w[i];
    int n = s_cnt[h];
    if (n > MAXNZ) n = MAXNZ;
    int k = 0;
    for (; k + 4 <= n; k += 4) {
        float p0 = s_val[h][k+0] * WT[(size_t)s_idx[h][k+0] * NBASE + i];
        float p1 = s_val[h][k+1] * WT[(size_t)s_idx[h][k+1] * NBASE + i];
        float p2 = s_val[h][k+2] * WT[(size_t)s_idx[h][k+2] * NBASE + i];
        float p3 = s_val[h][k+3] * WT[(size_t)s_idx[h][k+3] * NBASE + i];
        acc += (p0 + p1) + (p2 + p3);
    }
    for (; k < n; k++)
        acc += s_val[h][k] * WT[(size_t)s_idx[h][k] * NBASE + i];

    float pv = pov[b];
    int pos;
    if (h == 0) pos = (pv > 0.5f) ? i : (NBASE + i);
    else        pos = (pv > 0.5f) ? (NBASE + i) : i;
    g_base[(size_t)b * NH + pos] = fmaxf(acc, 0.0f);
}

// ---------------- a0 = relu(base @ W_a0^T + b_a0) ----------------
__global__ __launch_bounds__(256) void a0_kernel(const float* __restrict__ W_a0,
                                                 const float* __restrict__ b_a0)
{
    __shared__ float sA[16][64];
    __shared__ float sB[16][48];
    int m0 = blockIdx.x * 64;
    int n0 = blockIdx.y * 48;
    int t  = threadIdx.x;
    int tx = t % 16, ty = t / 16;
    float acc[4][3] = {};
    int am = t >> 2, ak = (t & 3) * 4;

    for (int kt = 0; kt < NH; kt += 16) {
        float4 av = *reinterpret_cast<const float4*>(&g_base[(size_t)(m0 + am) * NH + kt + ak]);
        float4 bv = make_float4(0.f, 0.f, 0.f, 0.f);
        if (t < 192) bv = *reinterpret_cast<const float4*>(&W_a0[(size_t)(n0 + am) * NH + kt + ak]);
        __syncthreads();
        sA[ak+0][am] = av.x; sA[ak+1][am] = av.y; sA[ak+2][am] = av.z; sA[ak+3][am] = av.w;
        if (t < 192) { sB[ak+0][am] = bv.x; sB[ak+1][am] = bv.y; sB[ak+2][am] = bv.z; sB[ak+3][am] = bv.w; }
        __syncthreads();
        #pragma unroll
        for (int k = 0; k < 16; k++) {
            float a[4], bb[3];
            #pragma unroll
            for (int ii = 0; ii < 4; ii++) a[ii] = sA[k][ty*4 + ii];
            #pragma unroll
            for (int j = 0; j < 3; j++)  bb[j] = sB[k][tx*3 + j];
            #pragma unroll
            for (int ii = 0; ii < 4; ii++)
                #pragma unroll
                for (int j = 0; j < 3; j++)
                    acc[ii][j] += a[ii] * bb[j];
        }
    }
    #pragma unroll
    for (int ii = 0; ii < 4; ii++) {
        int m = m0 + ty*4 + ii;
        #pragma unroll
        for (int j = 0; j < 3; j++) {
            int n = n0 + tx*3 + j;
            g_a0[(size_t)m * NA0 + n] = fmaxf(acc[ii][j] + b_a0[n], 0.0f);
        }
    }
}

// ---------------- value head ----------------
__global__ __launch_bounds__(256) void value_kernel(
    const float* __restrict__ b_v0,
    const float* __restrict__ W_v1, const float* __restrict__ b_v1,
    const float* __restrict__ W_v2, const float* __restrict__ b_v2,
    const float* __restrict__ W_vs, const float* __restrict__ b_vs,
    float* __restrict__ out)
{
    __shared__ float sbase[8][NH];
    __shared__ float sv0[8][32];
    int t  = threadIdx.x;
    int r0 = blockIdx.x * 8;
    for (int idx = t; idx < 8 * NH; idx += 256)
        sbase[idx / NH][idx % NH] = g_base[(size_t)(r0 + idx / NH) * NH + (idx % NH)];
    __syncthreads();

    int w = t / 32, lane = t % 32;
    const float* bp = sbase[w];

    float acc = b_v0[lane];
    const float* wp = g_WTv0 + lane;
    #pragma unroll 8
    for (int k = 0; k < NH; k++) acc += wp[(size_t)k * 32] * bp[k];
    sv0[w][lane] = fmaxf(acc, 0.0f);
    __syncwarp();

    float acc1 = b_v1[lane];
    #pragma unroll
    for (int j = 0; j < 32; j++) acc1 += W_v1[lane * 32 + j] * sv0[w][j];
    acc1 = fmaxf(acc1, 0.0f);

    float part = W_v2[lane] * acc1;
    for (int k = lane; k < NH; k += 32) part += W_vs[k] * bp[k];
    #pragma unroll
    for (int off = 16; off > 0; off >>= 1)
        part += __shfl_down_sync(0xffffffffu, part, off);
    if (lane == 0) out[r0 + w] = part + b_v2[0] + b_vs[0];
}

// ---------------- action head: fused K=720 GEMM via tf32 mma.sync ----------
// BM=BN=128, BK=16, 256 threads = 8 warps, each warp owns 64x32
// (4x4 grid of m16n8k8 tf32 tensor-core tiles).
__device__ __forceinline__ uint32_t f2tf32(float f) {
    uint32_t r;
    asm("cvt.rna.tf32.f32 %0, %1;" : "=r"(r) : "f"(f));
    return r;
}

#define SPITCH 132   // 128 + 4 pad: conflict-free fragment loads

__global__ __launch_bounds__(256, 2) void act_kernel(
    const float* __restrict__ W_a1, const float* __restrict__ b_a1,
    const float* __restrict__ W_as, const float* __restrict__ b_as,
    float* __restrict__ out)
{
    __shared__ uint32_t sA[16][SPITCH];
    __shared__ uint32_t sB[16][SPITCH];
    __shared__ float    sBias[128];

    int n0 = blockIdx.x * 128;
    int m0 = blockIdx.y * 128;
    int t  = threadIdx.x;
    int wid  = t >> 5;
    int lane = t & 31;
    int wm = wid >> 2;        // 0..1  -> 64-row slab
    int wn = wid & 3;         // 0..3  -> 32-col slab
    int mbase = wm * 64;
    int nbase = wn * 32;
    int r4 = lane >> 2;       // 0..7
    int c4 = lane & 3;        // 0..3

    int lr = t >> 1;          // loader row 0..127
    int lk = (t & 1) * 8;     // loader k-offset 0/8

    float acc[4][4][4] = {};  // [mt][nt][reg]

    // bias into smem (n0..n0+127)
    if (t < 128) sBias[t] = b_a1[n0 + t] + b_as[n0 + t];

    #pragma unroll 1
    for (int kt = 0; kt < KTOT / 16; kt++) {
        int kbase = kt * 16;
        const float *ap, *wp;
        if (kbase < NA0) {
            ap = &g_a0[(size_t)(m0 + lr) * NA0 + kbase + lk];
            wp = &W_a1[(size_t)(n0 + lr) * NA0 + kbase + lk];
        } else {
            int kb = kbase - NA0;
            ap = &g_base[(size_t)(m0 + lr) * NH + kb + lk];
            wp = &W_as[(size_t)(n0 + lr) * NH + kb + lk];
        }
        float4 av0 = *(const float4*)(ap);
        float4 av1 = *(const float4*)(ap + 4);
        float4 bv0 = *(const float4*)(wp);
        float4 bv1 = *(const float4*)(wp + 4);
        __syncthreads();
        sA[lk+0][lr] = f2tf32(av0.x); sA[lk+1][lr] = f2tf32(av0.y);
        sA[lk+2][lr] = f2tf32(av0.z); sA[lk+3][lr] = f2tf32(av0.w);
        sA[lk+4][lr] = f2tf32(av1.x); sA[lk+5][lr] = f2tf32(av1.y);
        sA[lk+6][lr] = f2tf32(av1.z); sA[lk+7][lr] = f2tf32(av1.w);
        sB[lk+0][lr] = f2tf32(bv0.x); sB[lk+1][lr] = f2tf32(bv0.y);
        sB[lk+2][lr] = f2tf32(bv0.z); sB[lk+3][lr] = f2tf32(bv0.w);
        sB[lk+4][lr] = f2tf32(bv1.x); sB[lk+5][lr] = f2tf32(bv1.y);
        sB[lk+6][lr] = f2tf32(bv1.z); sB[lk+7][lr] = f2tf32(bv1.w);
        __syncthreads();

        #pragma unroll
        for (int ks = 0; ks < 2; ks++) {
            int kc = ks * 8;
            uint32_t afr[4][4], bfr[4][2];
            #pragma unroll
            for (int mt = 0; mt < 4; mt++) {
                int mr = mbase + mt * 16 + r4;
                afr[mt][0] = sA[kc + c4    ][mr];
                afr[mt][1] = sA[kc + c4    ][mr + 8];
                afr[mt][2] = sA[kc + c4 + 4][mr];
                afr[mt][3] = sA[kc + c4 + 4][mr + 8];
            }
            #pragma unroll
            for (int nt = 0; nt < 4; nt++) {
                int nc = nbase + nt * 8 + r4;
                bfr[nt][0] = sB[kc + c4    ][nc];
                bfr[nt][1] = sB[kc + c4 + 4][nc];
            }
            #pragma unroll
            for (int mt = 0; mt < 4; mt++)
                #pragma unroll
                for (int nt = 0; nt < 4; nt++) {
                    asm volatile(
                        "mma.sync.aligned.m16n8k8.row.col.f32.tf32.tf32.f32 "
                        "{%0,%1,%2,%3}, {%4,%5,%6,%7}, {%8,%9}, {%0,%1,%2,%3};\n"
                        : "+f"(acc[mt][nt][0]), "+f"(acc[mt][nt][1]),
                          "+f"(acc[mt][nt][2]), "+f"(acc[mt][nt][3])
                        : "r"(afr[mt][0]), "r"(afr[mt][1]),
                          "r"(afr[mt][2]), "r"(afr[mt][3]),
                          "r"(bfr[nt][0]), "r"(bfr[nt][1]));
                }
        }
    }

    // epilogue: bias + store.  C layout: c0=(r4, 2*c4), c1=+1 col, c2/c3 = row+8.
    #pragma unroll
    for (int mt = 0; mt < 4; mt++) {
        int m = m0 + mbase + mt * 16 + r4;
        #pragma unroll
        for (int nt = 0; nt < 4; nt++) {
            int nl = nbase + nt * 8 + 2 * c4;
            float bi0 = sBias[nl], bi1 = sBias[nl + 1];
            float2 v0 = make_float2(acc[mt][nt][0] + bi0, acc[mt][nt][1] + bi1);
            float2 v1 = make_float2(acc[mt][nt][2] + bi0, acc[mt][nt][3] + bi1);
            *(float2*)&out[NB + (size_t)m       * NMOVE + n0 + nl] = v0;
            *(float2*)&out[NB + (size_t)(m + 8) * NMOVE + n0 + nl] = v1;
        }
    }
}

extern "C" void kernel_launch(void* const* d_in, const int* in_sizes, int n_in,
                              void* d_out, int out_size)
{
    const float* pov   = (const float*)d_in[0];
    const float* white = (const float*)d_in[1];
    const float* black = (const float*)d_in[2];
    const float* W_w   = (const float*)d_in[3];
    const float* b_w   = (const float*)d_in[4];
    const float* W_b   = (const float*)d_in[5];
    const float* b_b   = (const float*)d_in[6];
    const float* W_v0  = (const float*)d_in[7];
    const float* b_v0  = (const float*)d_in[8];
    const float* W_v1  = (const float*)d_in[9];
    const float* b_v1  = (const float*)d_in[10];
    const float* W_v2  = (const float*)d_in[11];
    const float* b_v2  = (const float*)d_in[12];
    const float* W_a0  = (const float*)d_in[13];
    const float* b_a0  = (const float*)d_in[14];
    const float* W_a1  = (const float*)d_in[15];
    const float* b_a1  = (const float*)d_in[16];
    const float* W_vs  = (const float*)d_in[17];
    const float* b_vs  = (const float*)d_in[18];
    const float* W_as  = (const float*)d_in[19];
    const float* b_as  = (const float*)d_in[20];
    float* out = (float*)d_out;

    dim3 tb(32, 8);
    transpose_kernel<<<dim3(ND / 32, NBASE / 32), tb>>>(W_w, NBASE, ND, 0);
    transpose_kernel<<<dim3(ND / 32, NBASE / 32), tb>>>(W_b, NBASE, ND, 1);
    transpose_kernel<<<dim3(NH / 32, 1), tb>>>(W_v0, 32, NH, 2);

    feature_kernel<<<NB, 2 * NBASE>>>(pov, white, black, b_w, b_b);
    a0_kernel<<<dim3(NB / 64, NA0 / 48), 256>>>(W_a0, b_a0);
    value_kernel<<<NB / 8, 256>>>(b_v0, W_v1, b_v1, W_v2, b_v2, W_vs, b_vs, out);
    act_kernel<<<dim3(NMOVE / 128, NB / 128), 256>>>(W_a1, b_a1, W_as, b_as, out);
}

// round 3
// speedup vs baseline: 1.3729x; 1.0847x over previous
#include <cuda_runtime.h>
#include <cstdint>

#define NB    2048
#define ND    40960
#define NBASE 288
#define NH    576     // 2*NBASE
#define NA0   144
#define NMOVE 4096
#define KP    736     // padded act K: [a0(144) pad(16) base(576)]
#define AOFF  160     // base starts here in g_actA rows
#define NSTG  46      // KP / 16

// -------- device scratch (no allocations allowed) --------
__device__ float g_WTw[(size_t)ND * NBASE];   // W_w^T  [D, 288]
__device__ float g_WTb[(size_t)ND * NBASE];   // W_b^T  [D, 288]
__device__ float g_WTv0[NH * 32];             // W_v0^T [576, 32]
__device__ float g_actA[(size_t)NB * KP];     // [relu(a0) | 0 | relu(base)] tf32-rounded
__device__ float g_actB[(size_t)NMOVE * KP];  // [W_a1 | 0 | W_as] tf32-rounded

__device__ __forceinline__ uint32_t f2tf32(float f) {
    uint32_t r;
    asm("cvt.rna.tf32.f32 %0, %1;" : "=r"(r) : "f"(f));
    return r;
}
__device__ __forceinline__ float tf32r(float f) { return __uint_as_float(f2tf32(f)); }

#define CP16(dst, src) asm volatile("cp.async.cg.shared.global [%0], [%1], 16;" :: "r"(dst), "l"(src))
#define CPCOMMIT()     asm volatile("cp.async.commit_group;")
#define CPWAIT(n)      asm volatile("cp.async.wait_group %0;" :: "n"(n))
#define LDSM4(R, addr) asm volatile( \
    "ldmatrix.sync.aligned.m8n8.x4.shared.b16 {%0,%1,%2,%3}, [%4];" \
    : "=r"((R)[0]), "=r"((R)[1]), "=r"((R)[2]), "=r"((R)[3]) : "r"(addr))

// ---------------- transpose: in[R,C] -> out[C,R] ----------------
__global__ void transpose_kernel(const float* __restrict__ in, int R, int C, int which) {
    float* out = (which == 0) ? g_WTw : (which == 1) ? g_WTb : g_WTv0;
    __shared__ float tile[32][33];
    int c0 = blockIdx.x * 32;
    int r0 = blockIdx.y * 32;
    int x = threadIdx.x;
    #pragma unroll
    for (int yy = threadIdx.y; yy < 32; yy += 8) {
        int r = r0 + yy, c = c0 + x;
        tile[yy][x] = (r < R && c < C) ? in[(size_t)r * C + c] : 0.0f;
    }
    __syncthreads();
    #pragma unroll
    for (int yy = threadIdx.y; yy < 32; yy += 8) {
        int c = c0 + yy, r = r0 + x;
        if (r < R && c < C) out[(size_t)c * R + r] = tile[x][yy];
    }
}

// ---------------- B-operand prep: g_actB = tf32([W_a1 | 0 | W_as]) ---------
__global__ __launch_bounds__(256) void bprep_kernel(const float* __restrict__ W_a1,
                                                    const float* __restrict__ W_as) {
    int n = blockIdx.x;
    for (int c = threadIdx.x; c < KP; c += 256) {
        float v = 0.0f;
        if (c < NA0)       v = W_a1[(size_t)n * NA0 + c];
        else if (c >= AOFF) v = W_as[(size_t)n * NH + (c - AOFF)];
        g_actB[(size_t)n * KP + c] = tf32r(v);
    }
}

// ---------------- feature transform + base ----------------
#define MAXNZ 1024
__global__ __launch_bounds__(2 * NBASE) void feature_kernel(
    const float* __restrict__ pov,
    const float* __restrict__ white,
    const float* __restrict__ black,
    const float* __restrict__ b_w,
    const float* __restrict__ b_b)
{
    __shared__ int   s_idx[2][MAXNZ];
    __shared__ float s_val[2][MAXNZ];
    __shared__ int   s_cnt[2];
    int b = blockIdx.x;
    int t = threadIdx.x;
    int h = t / NBASE;            // 0 = white, 1 = black
    int i = t - h * NBASE;
    if (t < 2) s_cnt[t] = 0;
    if (t < 16) g_actA[(size_t)b * KP + NA0 + t] = 0.0f;   // pad cols 144..159
    __syncthreads();

    const float* src = h ? black : white;
    const float4* row = reinterpret_cast<const float4*>(src + (size_t)b * ND);
    for (int u = i; u < ND / 4; u += NBASE) {
        float4 v = __ldcs(&row[u]);   // streaming: don't pollute L2
        if (v.x != 0.0f) { int p = atomicAdd(&s_cnt[h], 1); if (p < MAXNZ) { s_idx[h][p] = 4*u+0; s_val[h][p] = v.x; } }
        if (v.y != 0.0f) { int p = atomicAdd(&s_cnt[h], 1); if (p < MAXNZ) { s_idx[h][p] = 4*u+1; s_val[h][p] = v.y; } }
        if (v.z != 0.0f) { int p = atomicAdd(&s_cnt[h], 1); if (p < MAXNZ) { s_idx[h][p] = 4*u+2; s_val[h][p] = v.z; } }
        if (v.w != 0.0f) { int p = atomicAdd(&s_cnt[h], 1); if (p < MAXNZ) { s_idx[h][p] = 4*u+3; s_val[h][p] = v.w; } }
    }
    __syncthreads();

    const float* WT = h ? g_WTb : g_WTw;
    float acc = h ? b_b[i] : b_w[i];
    int n = s_cnt[h];
    if (n > MAXNZ) n = MAXNZ;
    int k = 0;
    for (; k + 4 <= n; k += 4) {
        float p0 = s_val[h][k+0] * WT[(size_t)s_idx[h][k+0] * NBASE + i];
        float p1 = s_val[h][k+1] * WT[(size_t)s_idx[h][k+1] * NBASE + i];
        float p2 = s_val[h][k+2] * WT[(size_t)s_idx[h][k+2] * NBASE + i];
        float p3 = s_val[h][k+3] * WT[(size_t)s_idx[h][k+3] * NBASE + i];
        acc += (p0 + p1) + (p2 + p3);
    }
    for (; k < n; k++)
        acc += s_val[h][k] * WT[(size_t)s_idx[h][k] * NBASE + i];

    float pv = pov[b];
    int pos;
    if (h == 0) pos = (pv > 0.5f) ? i : (NBASE + i);
    else        pos = (pv > 0.5f) ? (NBASE + i) : i;
    g_actA[(size_t)b * KP + AOFF + pos] = tf32r(fmaxf(acc, 0.0f));
}

// ---------------- a0 = relu(base @ W_a0^T + b_a0), tf32-rounded ------------
__global__ __launch_bounds__(256) void a0_kernel(const float* __restrict__ W_a0,
                                                 const float* __restrict__ b_a0)
{
    __shared__ float sA[16][64];
    __shared__ float sB[16][48];
    int m0 = blockIdx.x * 64;
    int n0 = blockIdx.y * 48;
    int t  = threadIdx.x;
    int tx = t % 16, ty = t / 16;
    float acc[4][3] = {};
    int am = t >> 2, ak = (t & 3) * 4;

    for (int kt = 0; kt < NH; kt += 16) {
        float4 av = *reinterpret_cast<const float4*>(&g_actA[(size_t)(m0 + am) * KP + AOFF + kt + ak]);
        float4 bv = make_float4(0.f, 0.f, 0.f, 0.f);
        if (t < 192) bv = *reinterpret_cast<const float4*>(&W_a0[(size_t)(n0 + am) * NH + kt + ak]);
        __syncthreads();
        sA[ak+0][am] = av.x; sA[ak+1][am] = av.y; sA[ak+2][am] = av.z; sA[ak+3][am] = av.w;
        if (t < 192) { sB[ak+0][am] = bv.x; sB[ak+1][am] = bv.y; sB[ak+2][am] = bv.z; sB[ak+3][am] = bv.w; }
        __syncthreads();
        #pragma unroll
        for (int k = 0; k < 16; k++) {
            float a[4], bb[3];
            #pragma unroll
            for (int ii = 0; ii < 4; ii++) a[ii] = sA[k][ty*4 + ii];
            #pragma unroll
            for (int j = 0; j < 3; j++)  bb[j] = sB[k][tx*3 + j];
            #pragma unroll
            for (int ii = 0; ii < 4; ii++)
                #pragma unroll
                for (int j = 0; j < 3; j++)
                    acc[ii][j] += a[ii] * bb[j];
        }
    }
    #pragma unroll
    for (int ii = 0; ii < 4; ii++) {
        int m = m0 + ty*4 + ii;
        #pragma unroll
        for (int j = 0; j < 3; j++) {
            int n = n0 + tx*3 + j;
            g_actA[(size_t)m * KP + n] = tf32r(fmaxf(acc[ii][j] + b_a0[n], 0.0f));
        }
    }
}

// ---------------- value head ----------------
__global__ __launch_bounds__(256) void value_kernel(
    const float* __restrict__ b_v0,
    const float* __restrict__ W_v1, const float* __restrict__ b_v1,
    const float* __restrict__ W_v2, const float* __restrict__ b_v2,
    const float* __restrict__ W_vs, const float* __restrict__ b_vs,
    float* __restrict__ out)
{
    __shared__ float sbase[8][NH];
    __shared__ float sv0[8][32];
    int t  = threadIdx.x;
    int r0 = blockIdx.x * 8;
    for (int idx = t; idx < 8 * NH; idx += 256)
        sbase[idx / NH][idx % NH] = g_actA[(size_t)(r0 + idx / NH) * KP + AOFF + (idx % NH)];
    __syncthreads();

    int w = t / 32, lane = t % 32;
    const float* bp = sbase[w];

    float acc = b_v0[lane];
    const float* wp = g_WTv0 + lane;
    #pragma unroll 8
    for (int k = 0; k < NH; k++) acc += wp[(size_t)k * 32] * bp[k];
    sv0[w][lane] = fmaxf(acc, 0.0f);
    __syncwarp();

    float acc1 = b_v1[lane];
    #pragma unroll
    for (int j = 0; j < 32; j++) acc1 += W_v1[lane * 32 + j] * sv0[w][j];
    acc1 = fmaxf(acc1, 0.0f);

    float part = W_v2[lane] * acc1;
    for (int k = lane; k < NH; k += 32) part += W_vs[k] * bp[k];
    #pragma unroll
    for (int off = 16; off > 0; off >>= 1)
        part += __shfl_down_sync(0xffffffffu, part, off);
    if (lane == 0) out[r0 + w] = part + b_v2[0] + b_vs[0];
}

// ---------------- action head: K=736 tf32 GEMM, cp.async + ldmatrix --------
// BM=BN=128, BK=16, 256 threads = 8 warps (2x4), warp tile 64x32.
// smem rows: 16 floats + 4 pad = 80B pitch -> conflict-free ldmatrix & STS.
#define SROW 20          // floats per smem row (80 bytes)
#define BUFSZ (128 * SROW * 4)  // bytes per buffer

__global__ __launch_bounds__(256, 2) void act_kernel(
    const float* __restrict__ b_a1, const float* __restrict__ b_as,
    float* __restrict__ out)
{
    __shared__ float sA[2][128 * SROW];
    __shared__ float sB[2][128 * SROW];
    __shared__ float sBias[128];

    int t = threadIdx.x;
    int lane = t & 31, wid = t >> 5;
    int n0 = blockIdx.x * 128, m0 = blockIdx.y * 128;
    int mbase = (wid >> 2) * 64;
    int nbase = (wid & 3) * 32;
    if (t < 128) sBias[t] = b_a1[n0 + t] + b_as[n0 + t];

    uint32_t saB = (uint32_t)__cvta_generic_to_shared(&sA[0][0]);
    uint32_t sbB = (uint32_t)__cvta_generic_to_shared(&sB[0][0]);

    // loader: 2 A-chunks + 2 B-chunks of 16B per thread per stage
    int r0c = t >> 2, g0 = t & 3;          // rows 0..63
    int r1c = r0c + 64;                    // rows 64..127
    const float* gA0 = g_actA + (size_t)(m0 + r0c) * KP + g0 * 4;
    const float* gA1 = g_actA + (size_t)(m0 + r1c) * KP + g0 * 4;
    const float* gB0 = g_actB + (size_t)(n0 + r0c) * KP + g0 * 4;
    const float* gB1 = g_actB + (size_t)(n0 + r1c) * KP + g0 * 4;
    uint32_t dA0 = saB + (r0c * SROW + g0 * 4) * 4;
    uint32_t dA1 = saB + (r1c * SROW + g0 * 4) * 4;
    uint32_t dB0 = sbB + (r0c * SROW + g0 * 4) * 4;
    uint32_t dB1 = sbB + (r1c * SROW + g0 * 4) * 4;

    // fragment lane addressing (80B pitch, no xor needed)
    int l7   = lane & 7;
    int aRow = mbase + ((lane >> 3) & 1) * 8 + l7;   // tile0/2: rows 0-7, tile1/3: 8-15
    int aK   = (lane >> 4) & 1;                      // tiles 2,3: k+4
    int bRow = ((lane >> 4) & 1) * 8 + l7;           // tiles 2,3: n+8
    int bK   = (lane >> 3) & 1;                      // tiles 1,3: k+4
    uint32_t aAddr[4], bAddr[2];
    #pragma unroll
    for (int mt = 0; mt < 4; mt++) aAddr[mt] = saB + ((aRow + mt * 16) * SROW) * 4 + aK * 16;
    #pragma unroll
    for (int p = 0; p < 2; p++)    bAddr[p]  = sbB + ((nbase + p * 16 + bRow) * SROW) * 4 + bK * 16;

    float acc[4][4][4] = {};

    // prologue: stage 0
    CP16(dA0, gA0); CP16(dA1, gA1); CP16(dB0, gB0); CP16(dB1, gB1);
    CPCOMMIT();

    for (int s = 0; s < NSTG; s++) {
        if (s + 1 < NSTG) {
            int nb = (s + 1) & 1;
            int ko = (s + 1) * 16;
            uint32_t bo = nb * BUFSZ;
            CP16(dA0 + bo, gA0 + ko); CP16(dA1 + bo, gA1 + ko);
            CP16(dB0 + bo, gB0 + ko); CP16(dB1 + bo, gB1 + ko);
            CPCOMMIT();
            CPWAIT(1);
        } else {
            CPWAIT(0);
        }
        __syncthreads();

        uint32_t bo = (s & 1) * BUFSZ;
        #pragma unroll
        for (int ks = 0; ks < 2; ks++) {
            uint32_t kb = bo + ks * 32;        // kgrp advance: 8 k = 2 chunks = 32B
            uint32_t afr[4][4];
            #pragma unroll
            for (int mt = 0; mt < 4; mt++) LDSM4(afr[mt], aAddr[mt] + kb);
            uint32_t bfr[4][2];
            #pragma unroll
            for (int p = 0; p < 2; p++) {
                uint32_t r[4];
                LDSM4(r, bAddr[p] + kb);
                bfr[2*p][0] = r[0]; bfr[2*p][1] = r[1];
                bfr[2*p+1][0] = r[2]; bfr[2*p+1][1] = r[3];
            }
            #pragma unroll
            for (int mt = 0; mt < 4; mt++)
                #pragma unroll
                for (int nt = 0; nt < 4; nt++) {
                    asm volatile(
                        "mma.sync.aligned.m16n8k8.row.col.f32.tf32.tf32.f32 "
                        "{%0,%1,%2,%3}, {%4,%5,%6,%7}, {%8,%9}, {%0,%1,%2,%3};\n"
                        : "+f"(acc[mt][nt][0]), "+f"(acc[mt][nt][1]),
                          "+f"(acc[mt][nt][2]), "+f"(acc[mt][nt][3])
                        : "r"(afr[mt][0]), "r"(afr[mt][1]),
                          "r"(afr[mt][2]), "r"(afr[mt][3]),
                          "r"(bfr[nt][0]), "r"(bfr[nt][1]));
                }
        }
        __syncthreads();
    }

    // epilogue: bias + streaming store
    int r4 = lane >> 2, c4 = lane & 3;
    #pragma unroll
    for (int mt = 0; mt < 4; mt++) {
        int m = m0 + mbase + mt * 16 + r4;
        #pragma unroll
        for (int nt = 0; nt < 4; nt++) {
            int nl = nbase + nt * 8 + 2 * c4;
            float bi0 = sBias[nl], bi1 = sBias[nl + 1];
            float2 v0 = make_float2(acc[mt][nt][0] + bi0, acc[mt][nt][1] + bi1);
            float2 v1 = make_float2(acc[mt][nt][2] + bi0, acc[mt][nt][3] + bi1);
            __stcs((float2*)&out[NB + (size_t)m       * NMOVE + n0 + nl], v0);
            __stcs((float2*)&out[NB + (size_t)(m + 8) * NMOVE + n0 + nl], v1);
        }
    }
}

extern "C" void kernel_launch(void* const* d_in, const int* in_sizes, int n_in,
                              void* d_out, int out_size)
{
    const float* pov   = (const float*)d_in[0];
    const float* white = (const float*)d_in[1];
    const float* black = (const float*)d_in[2];
    const float* W_w   = (const float*)d_in[3];
    const float* b_w   = (const float*)d_in[4];
    const float* W_b   = (const float*)d_in[5];
    const float* b_b   = (const float*)d_in[6];
    const float* W_v0  = (const float*)d_in[7];
    const float* b_v0  = (const float*)d_in[8];
    const float* W_v1  = (const float*)d_in[9];
    const float* b_v1  = (const float*)d_in[10];
    const float* W_v2  = (const float*)d_in[11];
    const float* b_v2  = (const float*)d_in[12];
    const float* W_a0  = (const float*)d_in[13];
    const float* b_a0  = (const float*)d_in[14];
    const float* W_a1  = (const float*)d_in[15];
    const float* b_a1  = (const float*)d_in[16];
    const float* W_vs  = (const float*)d_in[17];
    const float* b_vs  = (const float*)d_in[18];
    const float* W_as  = (const float*)d_in[19];
    const float* b_as  = (const float*)d_in[20];
    float* out = (float*)d_out;

    dim3 tb(32, 8);
    transpose_kernel<<<dim3(ND / 32, NBASE / 32), tb>>>(W_w, NBASE, ND, 0);
    transpose_kernel<<<dim3(ND / 32, NBASE / 32), tb>>>(W_b, NBASE, ND, 1);
    transpose_kernel<<<dim3(NH / 32, 1), tb>>>(W_v0, 32, NH, 2);
    bprep_kernel<<<NMOVE, 256>>>(W_a1, W_as);

    feature_kernel<<<NB, 2 * NBASE>>>(pov, white, black, b_w, b_b);
    a0_kernel<<<dim3(NB / 64, NA0 / 48), 256>>>(W_a0, b_a0);
    value_kernel<<<NB / 8, 256>>>(b_v0, W_v1, b_v1, W_v2, b_v2, W_vs, b_vs, out);
    act_kernel<<<dim3(NMOVE / 128, NB / 128), 256>>>(b_a1, b_as, out);
}

// round 5
// speedup vs baseline: 1.5466x; 1.1265x over previous
#include <cuda_runtime.h>
#include <cuda_fp16.h>
#include <cstdint>

#define NB    2048
#define ND    40960
#define NBASE 288
#define NH    576     // 2*NBASE
#define NA0   144
#define NMOVE 4096
#define KP    736     // padded act K: [a0(144) pad(16) base(576)]
#define AOFF  160     // base starts here
#define NSTG  23      // K chunks of 32 halfs (64B rows)

// -------- device scratch (no allocations allowed) --------
__device__ float  g_WTw[(size_t)ND * NBASE];    // W_w^T  [D, 288]
__device__ float  g_WTb[(size_t)ND * NBASE];    // W_b^T  [D, 288]
__device__ float  g_WTv0[NH * 32];              // W_v0^T [576, 32]
__device__ float  g_base[(size_t)NB * NH];      // relu'd base, fp32 (a0 + value head)
__device__ __half g_actA_h[(size_t)NB * KP];    // [relu(a0) | 0 | relu(base)] fp16
__device__ __half g_actB_h[(size_t)NMOVE * KP]; // [W_a1 | 0 | W_as] fp16

#define CP16(dst, src) asm volatile("cp.async.cg.shared.global [%0], [%1], 16;" :: "r"(dst), "l"(src))
#define CPCOMMIT()     asm volatile("cp.async.commit_group;")
#define CPWAIT(n)      asm volatile("cp.async.wait_group %0;" :: "n"(n))
#define LDSM4(R, addr) asm volatile( \
    "ldmatrix.sync.aligned.m8n8.x4.shared.b16 {%0,%1,%2,%3}, [%4];" \
    : "=r"((R)[0]), "=r"((R)[1]), "=r"((R)[2]), "=r"((R)[3]) : "r"(addr))

// ---------------- transpose: in[R,C] -> out[C,R] ----------------
__global__ void transpose_kernel(const float* __restrict__ in, int R, int C, int which) {
    float* out = (which == 0) ? g_WTw : (which == 1) ? g_WTb : g_WTv0;
    __shared__ float tile[32][33];
    int c0 = blockIdx.x * 32;
    int r0 = blockIdx.y * 32;
    int x = threadIdx.x;
    #pragma unroll
    for (int yy = threadIdx.y; yy < 32; yy += 8) {
        int r = r0 + yy, c = c0 + x;
        tile[yy][x] = (r < R && c < C) ? in[(size_t)r * C + c] : 0.0f;
    }
    __syncthreads();
    #pragma unroll
    for (int yy = threadIdx.y; yy < 32; yy += 8) {
        int c = c0 + yy, r = r0 + x;
        if (r < R && c < C) out[(size_t)c * R + r] = tile[x][yy];
    }
}

// ---------------- B-operand prep: g_actB_h = fp16([W_a1 | 0 | W_as]) -------
__global__ __launch_bounds__(256) void bprep_kernel(const float* __restrict__ W_a1,
                                                    const float* __restrict__ W_as) {
    int n = blockIdx.x;
    for (int c = threadIdx.x; c < KP; c += 256) {
        float v = 0.0f;
        if (c < NA0)        v = W_a1[(size_t)n * NA0 + c];
        else if (c >= AOFF) v = W_as[(size_t)n * NH + (c - AOFF)];
        g_actB_h[(size_t)n * KP + c] = __float2half(v);
    }
}

// ---------------- feature transform + base ----------------
#define MAXNZ 1024
__global__ __launch_bounds__(2 * NBASE) void feature_kernel(
    const float* __restrict__ pov,
    const float* __restrict__ white,
    const float* __restrict__ black,
    const float* __restrict__ b_w,
    const float* __restrict__ b_b)
{
    __shared__ int   s_idx[2][MAXNZ];
    __shared__ float s_val[2][MAXNZ];
    __shared__ int   s_cnt[2];
    int b = blockIdx.x;
    int t = threadIdx.x;
    int h = t / NBASE;
    int i = t - h * NBASE;
    if (t < 2) s_cnt[t] = 0;
    if (t < 16) g_actA_h[(size_t)b * KP + NA0 + t] = __float2half(0.0f);
    __syncthreads();

    const float* src = h ? black : white;
    const float4* row = reinterpret_cast<const float4*>(src + (size_t)b * ND);
    for (int u = i; u < ND / 4; u += NBASE) {
        float4 v = __ldcs(&row[u]);
        if (v.x != 0.0f) { int p = atomicAdd(&s_cnt[h], 1); if (p < MAXNZ) { s_idx[h][p] = 4*u+0; s_val[h][p] = v.x; } }
        if (v.y != 0.0f) { int p = atomicAdd(&s_cnt[h], 1); if (p < MAXNZ) { s_idx[h][p] = 4*u+1; s_val[h][p] = v.y; } }
        if (v.z != 0.0f) { int p = atomicAdd(&s_cnt[h], 1); if (p < MAXNZ) { s_idx[h][p] = 4*u+2; s_val[h][p] = v.z; } }
        if (v.w != 0.0f) { int p = atomicAdd(&s_cnt[h], 1); if (p < MAXNZ) { s_idx[h][p] = 4*u+3; s_val[h][p] = v.w; } }
    }
    __syncthreads();

    const float* WT = h ? g_WTb : g_WTw;
    float acc = h ? b_b[i] : b_w[i];
    int n = s_cnt[h];
    if (n > MAXNZ) n = MAXNZ;
    int k = 0;
    for (; k + 4 <= n; k += 4) {
        float p0 = s_val[h][k+0] * WT[(size_t)s_idx[h][k+0] * NBASE + i];
        float p1 = s_val[h][k+1] * WT[(size_t)s_idx[h][k+1] * NBASE + i];
        float p2 = s_val[h][k+2] * WT[(size_t)s_idx[h][k+2] * NBASE + i];
        float p3 = s_val[h][k+3] * WT[(size_t)s_idx[h][k+3] * NBASE + i];
        acc += (p0 + p1) + (p2 + p3);
    }
    for (; k < n; k++)
        acc += s_val[h][k] * WT[(size_t)s_idx[h][k] * NBASE + i];

    float pv = pov[b];
    int pos;
    if (h == 0) pos = (pv > 0.5f) ? i : (NBASE + i);
    else        pos = (pv > 0.5f) ? (NBASE + i) : i;
    float r = fmaxf(acc, 0.0f);
    g_base[(size_t)b * NH + pos] = r;
    g_actA_h[(size_t)b * KP + AOFF + pos] = __float2half(r);
}

// ---------------- a0 = relu(base @ W_a0^T + b_a0) -> fp16 ------------------
__global__ __launch_bounds__(256) void a0_kernel(const float* __restrict__ W_a0,
                                                 const float* __restrict__ b_a0)
{
    __shared__ float sA[16][64];
    __shared__ float sB[16][48];
    int m0 = blockIdx.x * 64;
    int n0 = blockIdx.y * 48;
    int t  = threadIdx.x;
    int tx = t % 16, ty = t / 16;
    float acc[4][3] = {};
    int am = t >> 2, ak = (t & 3) * 4;

    for (int kt = 0; kt < NH; kt += 16) {
        float4 av = *reinterpret_cast<const float4*>(&g_base[(size_t)(m0 + am) * NH + kt + ak]);
        float4 bv = make_float4(0.f, 0.f, 0.f, 0.f);
        if (t < 192) bv = *reinterpret_cast<const float4*>(&W_a0[(size_t)(n0 + am) * NH + kt + ak]);
        __syncthreads();
        sA[ak+0][am] = av.x; sA[ak+1][am] = av.y; sA[ak+2][am] = av.z; sA[ak+3][am] = av.w;
        if (t < 192) { sB[ak+0][am] = bv.x; sB[ak+1][am] = bv.y; sB[ak+2][am] = bv.z; sB[ak+3][am] = bv.w; }
        __syncthreads();
        #pragma unroll
        for (int k = 0; k < 16; k++) {
            float a[4], bb[3];
            #pragma unroll
            for (int ii = 0; ii < 4; ii++) a[ii] = sA[k][ty*4 + ii];
            #pragma unroll
            for (int j = 0; j < 3; j++)  bb[j] = sB[k][tx*3 + j];
            #pragma unroll
            for (int ii = 0; ii < 4; ii++)
                #pragma unroll
                for (int j = 0; j < 3; j++)
                    acc[ii][j] += a[ii] * bb[j];
        }
    }
    #pragma unroll
    for (int ii = 0; ii < 4; ii++) {
        int m = m0 + ty*4 + ii;
        #pragma unroll
        for (int j = 0; j < 3; j++) {
            int n = n0 + tx*3 + j;
            g_actA_h[(size_t)m * KP + n] = __float2half(fmaxf(acc[ii][j] + b_a0[n], 0.0f));
        }
    }
}

// ---------------- value head (fp32, exact) ----------------
__global__ __launch_bounds__(256) void value_kernel(
    const float* __restrict__ b_v0,
    const float* __restrict__ W_v1, const float* __restrict__ b_v1,
    const float* __restrict__ W_v2, const float* __restrict__ b_v2,
    const float* __restrict__ W_vs, const float* __restrict__ b_vs,
    float* __restrict__ out)
{
    __shared__ float sbase[8][NH];
    __shared__ float sv0[8][32];
    int t  = threadIdx.x;
    int r0 = blockIdx.x * 8;
    for (int idx = t; idx < 8 * NH; idx += 256)
        sbase[idx / NH][idx % NH] = g_base[(size_t)(r0 + idx / NH) * NH + (idx % NH)];
    __syncthreads();

    int w = t / 32, lane = t % 32;
    const float* bp = sbase[w];

    float acc = b_v0[lane];
    const float* wp = g_WTv0 + lane;
    #pragma unroll 8
    for (int k = 0; k < NH; k++) acc += wp[(size_t)k * 32] * bp[k];
    sv0[w][lane] = fmaxf(acc, 0.0f);
    __syncwarp();

    float acc1 = b_v1[lane];
    #pragma unroll
    for (int j = 0; j < 32; j++) acc1 += W_v1[lane * 32 + j] * sv0[w][j];
    acc1 = fmaxf(acc1, 0.0f);

    float part = W_v2[lane] * acc1;
    for (int k = lane; k < NH; k += 32) part += W_vs[k] * bp[k];
    #pragma unroll
    for (int off = 16; off > 0; off >>= 1)
        part += __shfl_down_sync(0xffffffffu, part, off);
    if (lane == 0) out[r0 + w] = part + b_v2[0] + b_vs[0];
}

// ---------------- action head: K=736 fp16 GEMM, cp.async + ldmatrix --------
// BM=BN=128, BK=32 halfs (64B rows), 256 threads = 8 warps (2x4), warp 64x32.
// smem pitch: 32 halfs + 8 pad = 80B -> conflict-free STS.128 & ldmatrix.
#define SROWH 40                 // halfs per smem row (80 bytes)
#define BUFB  (128 * 80)         // bytes per buffer

__global__ __launch_bounds__(256, 2) void act_kernel(
    const float* __restrict__ b_a1, const float* __restrict__ b_as,
    float* __restrict__ out)
{
    __shared__ __align__(16) __half sA[2][128 * SROWH];
    __shared__ __align__(16) __half sB[2][128 * SROWH];
    __shared__ float sBias[128];

    int t = threadIdx.x;
    int lane = t & 31, wid = t >> 5;
    int n0 = blockIdx.x * 128, m0 = blockIdx.y * 128;
    int mbase = (wid >> 2) * 64;
    int nbase = (wid & 3) * 32;
    if (t < 128) sBias[t] = b_a1[n0 + t] + b_as[n0 + t];

    uint32_t saB = (uint32_t)__cvta_generic_to_shared(&sA[0][0]);
    uint32_t sbB = (uint32_t)__cvta_generic_to_shared(&sB[0][0]);

    // loader: per stage each thread copies 2 A-chunks + 2 B-chunks of 16B
    int r0c = t >> 2, g0 = t & 3;          // rows 0..63, 16B group 0..3
    int r1c = r0c + 64;                    // rows 64..127
    const __half* gA0 = g_actA_h + (size_t)(m0 + r0c) * KP + g0 * 8;
    const __half* gA1 = g_actA_h + (size_t)(m0 + r1c) * KP + g0 * 8;
    const __half* gB0 = g_actB_h + (size_t)(n0 + r0c) * KP + g0 * 8;
    const __half* gB1 = g_actB_h + (size_t)(n0 + r1c) * KP + g0 * 8;
    uint32_t dA0 = saB + r0c * 80 + g0 * 16;
    uint32_t dA1 = saB + r1c * 80 + g0 * 16;
    uint32_t dB0 = sbB + r0c * 80 + g0 * 16;
    uint32_t dB1 = sbB + r1c * 80 + g0 * 16;

    // ldmatrix lane addressing (80B pitch, conflict-free)
    int l7 = lane & 7;
    int aRow = mbase + ((lane >> 3) & 1) * 8 + l7;   // sel&1 -> m+8
    int aK   = (lane >> 4) & 1;                      // sel>>1 -> k+8 (16B)
    int bRow = ((lane >> 4) & 1) * 8 + l7;           // sel>>1 -> n+8
    int bK   = (lane >> 3) & 1;                      // sel&1 -> k+8 (16B)
    uint32_t aAddr[4], bAddr[2];
    #pragma unroll
    for (int mt = 0; mt < 4; mt++) aAddr[mt] = saB + (aRow + mt * 16) * 80 + aK * 16;
    #pragma unroll
    for (int p = 0; p < 2; p++)    bAddr[p]  = sbB + (nbase + p * 16 + bRow) * 80 + bK * 16;

    float acc[4][4][4] = {};

    // prologue: stage 0 into buffer 0
    CP16(dA0, gA0); CP16(dA1, gA1); CP16(dB0, gB0); CP16(dB1, gB1);
    CPCOMMIT();

    for (int s = 0; s < NSTG; s++) {
        if (s + 1 < NSTG) {
            uint32_t bo = ((s + 1) & 1) * BUFB;
            int ko = (s + 1) * 32;                  // halfs
            CP16(dA0 + bo, gA0 + ko); CP16(dA1 + bo, gA1 + ko);
            CP16(dB0 + bo, gB0 + ko); CP16(dB1 + bo, gB1 + ko);
            CPCOMMIT();
            CPWAIT(1);
        } else {
            CPWAIT(0);
        }
        __syncthreads();

        uint32_t bo = (s & 1) * BUFB;
        #pragma unroll
        for (int ks = 0; ks < 2; ks++) {
            uint32_t kb = bo + ks * 32;            // +16 halfs = 32B
            uint32_t afr[4][4];
            #pragma unroll
            for (int mt = 0; mt < 4; mt++) LDSM4(afr[mt], aAddr[mt] + kb);
            uint32_t bfr[4][2];
            #pragma unroll
            for (int p = 0; p < 2; p++) {
                uint32_t r[4];
                LDSM4(r, bAddr[p] + kb);
                bfr[2*p][0]   = r[0]; bfr[2*p][1]   = r[1];
                bfr[2*p+1][0] = r[2]; bfr[2*p+1][1] = r[3];
            }
            #pragma unroll
            for (int mt = 0; mt < 4; mt++)
                #pragma unroll
                for (int nt = 0; nt < 4; nt++) {
                    asm volatile(
                        "mma.sync.aligned.m16n8k16.row.col.f32.f16.f16.f32 "
                        "{%0,%1,%2,%3}, {%4,%5,%6,%7}, {%8,%9}, {%0,%1,%2,%3};\n"
                        : "+f"(acc[mt][nt][0]), "+f"(acc[mt][nt][1]),
                          "+f"(acc[mt][nt][2]), "+f"(acc[mt][nt][3])
                        : "r"(afr[mt][0]), "r"(afr[mt][1]),
                          "r"(afr[mt][2]), "r"(afr[mt][3]),
                          "r"(bfr[nt][0]), "r"(bfr[nt][1]));
                }
        }
        __syncthreads();
    }

    // epilogue: bias + streaming store
    int r4 = lane >> 2, c4 = lane & 3;
    #pragma unroll
    for (int mt = 0; mt < 4; mt++) {
        int m = m0 + mbase + mt * 16 + r4;
        #pragma unroll
        for (int nt = 0; nt < 4; nt++) {
            int nl = nbase + nt * 8 + 2 * c4;
            float bi0 = sBias[nl], bi1 = sBias[nl + 1];
            float2 v0 = make_float2(acc[mt][nt][0] + bi0, acc[mt][nt][1] + bi1);
            float2 v1 = make_float2(acc[mt][nt][2] + bi0, acc[mt][nt][3] + bi1);
            __stcs((float2*)&out[NB + (size_t)m       * NMOVE + n0 + nl], v0);
            __stcs((float2*)&out[NB + (size_t)(m + 8) * NMOVE + n0 + nl], v1);
        }
    }
}

extern "C" void kernel_launch(void* const* d_in, const int* in_sizes, int n_in,
                              void* d_out, int out_size)
{
    const float* pov   = (const float*)d_in[0];
    const float* white = (const float*)d_in[1];
    const float* black = (const float*)d_in[2];
    const float* W_w   = (const float*)d_in[3];
    const float* b_w   = (const float*)d_in[4];
    const float* W_b   = (const float*)d_in[5];
    const float* b_b   = (const float*)d_in[6];
    const float* W_v0  = (const float*)d_in[7];
    const float* b_v0  = (const float*)d_in[8];
    const float* W_v1  = (const float*)d_in[9];
    const float* b_v1  = (const float*)d_in[10];
    const float* W_v2  = (const float*)d_in[11];
    const float* b_v2  = (const float*)d_in[12];
    const float* W_a0  = (const float*)d_in[13];
    const float* b_a0  = (const float*)d_in[14];
    const float* W_a1  = (const float*)d_in[15];
    const float* b_a1  = (const float*)d_in[16];
    const float* W_vs  = (const float*)d_in[17];
    const float* b_vs  = (const float*)d_in[18];
    const float* W_as  = (const float*)d_in[19];
    const float* b_as  = (const float*)d_in[20];
    float* out = (float*)d_out;

    dim3 tb(32, 8);
    transpose_kernel<<<dim3(ND / 32, NBASE / 32), tb>>>(W_w, NBASE, ND, 0);
    transpose_kernel<<<dim3(ND / 32, NBASE / 32), tb>>>(W_b, NBASE, ND, 1);
    transpose_kernel<<<dim3(NH / 32, 1), tb>>>(W_v0, 32, NH, 2);
    bprep_kernel<<<NMOVE, 256>>>(W_a1, W_as);

    feature_kernel<<<NB, 2 * NBASE>>>(pov, white, black, b_w, b_b);
    a0_kernel<<<dim3(NB / 64, NA0 / 48), 256>>>(W_a0, b_a0);
    value_kernel<<<NB / 8, 256>>>(b_v0, W_v1, b_v1, W_v2, b_v2, W_vs, b_vs, out);
    act_kernel<<<dim3(NMOVE / 128, NB / 128), 256>>>(b_a1, b_as, out);
}

// round 6
// speedup vs baseline: 1.7610x; 1.1386x over previous
#include <cuda_runtime.h>
#include <cuda_fp16.h>
#include <cstdint>

#define NB    2048
#define ND    40960
#define NBASE 288
#define NH    576     // 2*NBASE
#define NA0   144
#define NMOVE 4096
#define KP    736     // padded act K: [a0(144) pad(16) base(576)]
#define AOFF  160     // base starts here
#define NSTG  23      // K chunks of 32 halfs (64B rows)

// -------- device scratch (no allocations allowed) --------
__device__ float  g_WTw[(size_t)ND * NBASE];    // W_w^T  [D, 288]
__device__ float  g_WTb[(size_t)ND * NBASE];    // W_b^T  [D, 288]
__device__ float  g_WTv0[NH * 32];              // W_v0^T [576, 32]
__device__ float  g_base[(size_t)NB * NH];      // relu'd base, fp32
__device__ __half g_actA_h[(size_t)NB * KP];    // [relu(a0) | 0 | relu(base)] fp16
__device__ __half g_actB_h[(size_t)NMOVE * KP]; // [W_a1 | 0 | W_as] fp16

#define CP16(dst, src) asm volatile("cp.async.cg.shared.global [%0], [%1], 16;" :: "r"(dst), "l"(src))
#define CPCOMMIT()     asm volatile("cp.async.commit_group;")
#define CPWAIT(n)      asm volatile("cp.async.wait_group %0;" :: "n"(n))
#define LDSM4(R, addr) asm volatile( \
    "ldmatrix.sync.aligned.m8n8.x4.shared.b16 {%0,%1,%2,%3}, [%4];" \
    : "=r"((R)[0]), "=r"((R)[1]), "=r"((R)[2]), "=r"((R)[3]) : "r"(addr))

// ---------------- transpose: in[R,C] -> out[C,R] ----------------
__global__ void transpose_kernel(const float* __restrict__ in, int R, int C, int which) {
    float* out = (which == 0) ? g_WTw : (which == 1) ? g_WTb : g_WTv0;
    __shared__ float tile[32][33];
    int c0 = blockIdx.x * 32;
    int r0 = blockIdx.y * 32;
    int x = threadIdx.x;
    #pragma unroll
    for (int yy = threadIdx.y; yy < 32; yy += 8) {
        int r = r0 + yy, c = c0 + x;
        tile[yy][x] = (r < R && c < C) ? in[(size_t)r * C + c] : 0.0f;
    }
    __syncthreads();
    #pragma unroll
    for (int yy = threadIdx.y; yy < 32; yy += 8) {
        int c = c0 + yy, r = r0 + x;
        if (r < R && c < C) out[(size_t)c * R + r] = tile[x][yy];
    }
}

// ---------------- B-operand prep: g_actB_h = fp16([W_a1 | 0 | W_as]) -------
__global__ __launch_bounds__(256) void bprep_kernel(const float* __restrict__ W_a1,
                                                    const float* __restrict__ W_as) {
    int n = blockIdx.x;
    for (int c = threadIdx.x; c < KP; c += 256) {
        float v = 0.0f;
        if (c < NA0)        v = W_a1[(size_t)n * NA0 + c];
        else if (c >= AOFF) v = W_as[(size_t)n * NH + (c - AOFF)];
        g_actB_h[(size_t)n * KP + c] = __float2half(v);
    }
}

// ---------------- feature transform + base ----------------
// One block per (batch row, color): grid = NB*2, 288 threads.
// Phase 1: scan 40960-wide mask; Phase 2: coalesced gather-sum.
#define MAXNZ 512
__global__ __launch_bounds__(NBASE) void feature_kernel(
    const float* __restrict__ pov,
    const float* __restrict__ white,
    const float* __restrict__ black,
    const float* __restrict__ b_w,
    const float* __restrict__ b_b)
{
    __shared__ int   s_idx[MAXNZ];
    __shared__ float s_val[MAXNZ];
    __shared__ int   s_cnt;
    int b = blockIdx.x >> 1;
    int h = blockIdx.x & 1;       // 0 = white, 1 = black
    int i = threadIdx.x;
    if (i == 0) s_cnt = 0;
    if (h == 0 && i < 16) g_actA_h[(size_t)b * KP + NA0 + i] = __float2half(0.0f);
    __syncthreads();

    const float* src = h ? black : white;
    const float4* row = reinterpret_cast<const float4*>(src + (size_t)b * ND);
    for (int u = i; u < ND / 4; u += NBASE) {
        float4 v = __ldcs(&row[u]);
        if (v.x != 0.0f) { int p = atomicAdd(&s_cnt, 1); if (p < MAXNZ) { s_idx[p] = 4*u+0; s_val[p] = v.x; } }
        if (v.y != 0.0f) { int p = atomicAdd(&s_cnt, 1); if (p < MAXNZ) { s_idx[p] = 4*u+1; s_val[p] = v.y; } }
        if (v.z != 0.0f) { int p = atomicAdd(&s_cnt, 1); if (p < MAXNZ) { s_idx[p] = 4*u+2; s_val[p] = v.z; } }
        if (v.w != 0.0f) { int p = atomicAdd(&s_cnt, 1); if (p < MAXNZ) { s_idx[p] = 4*u+3; s_val[p] = v.w; } }
    }
    __syncthreads();

    const float* WT = h ? g_WTb : g_WTw;
    float acc = h ? b_b[i] : b_w[i];
    int n = s_cnt;
    if (n > MAXNZ) n = MAXNZ;
    int k = 0;
    for (; k + 4 <= n; k += 4) {
        float p0 = s_val[k+0] * WT[(size_t)s_idx[k+0] * NBASE + i];
        float p1 = s_val[k+1] * WT[(size_t)s_idx[k+1] * NBASE + i];
        float p2 = s_val[k+2] * WT[(size_t)s_idx[k+2] * NBASE + i];
        float p3 = s_val[k+3] * WT[(size_t)s_idx[k+3] * NBASE + i];
        acc += (p0 + p1) + (p2 + p3);
    }
    for (; k < n; k++)
        acc += s_val[k] * WT[(size_t)s_idx[k] * NBASE + i];

    float pv = pov[b];
    int pos;
    if (h == 0) pos = (pv > 0.5f) ? i : (NBASE + i);
    else        pos = (pv > 0.5f) ? (NBASE + i) : i;
    float r = fmaxf(acc, 0.0f);
    g_base[(size_t)b * NH + pos] = r;
    g_actA_h[(size_t)b * KP + AOFF + pos] = __float2half(r);
}

// ---------------- a0 = relu(base @ W_a0^T + b_a0) -> fp16 ------------------
__global__ __launch_bounds__(256) void a0_kernel(const float* __restrict__ W_a0,
                                                 const float* __restrict__ b_a0)
{
    __shared__ float sA[16][64];
    __shared__ float sB[16][48];
    int m0 = blockIdx.x * 64;
    int n0 = blockIdx.y * 48;
    int t  = threadIdx.x;
    int tx = t % 16, ty = t / 16;
    float acc[4][3] = {};
    int am = t >> 2, ak = (t & 3) * 4;

    for (int kt = 0; kt < NH; kt += 16) {
        float4 av = *reinterpret_cast<const float4*>(&g_base[(size_t)(m0 + am) * NH + kt + ak]);
        float4 bv = make_float4(0.f, 0.f, 0.f, 0.f);
        if (t < 192) bv = *reinterpret_cast<const float4*>(&W_a0[(size_t)(n0 + am) * NH + kt + ak]);
        __syncthreads();
        sA[ak+0][am] = av.x; sA[ak+1][am] = av.y; sA[ak+2][am] = av.z; sA[ak+3][am] = av.w;
        if (t < 192) { sB[ak+0][am] = bv.x; sB[ak+1][am] = bv.y; sB[ak+2][am] = bv.z; sB[ak+3][am] = bv.w; }
        __syncthreads();
        #pragma unroll
        for (int k = 0; k < 16; k++) {
            float a[4], bb[3];
            #pragma unroll
            for (int ii = 0; ii < 4; ii++) a[ii] = sA[k][ty*4 + ii];
            #pragma unroll
            for (int j = 0; j < 3; j++)  bb[j] = sB[k][tx*3 + j];
            #pragma unroll
            for (int ii = 0; ii < 4; ii++)
                #pragma unroll
                for (int j = 0; j < 3; j++)
                    acc[ii][j] += a[ii] * bb[j];
        }
    }
    #pragma unroll
    for (int ii = 0; ii < 4; ii++) {
        int m = m0 + ty*4 + ii;
        #pragma unroll
        for (int j = 0; j < 3; j++) {
            int n = n0 + tx*3 + j;
            g_actA_h[(size_t)m * KP + n] = __float2half(fmaxf(acc[ii][j] + b_a0[n], 0.0f));
        }
    }
}

// ---------------- value head (fp32, exact) ----------------
__global__ __launch_bounds__(256) void value_kernel(
    const float* __restrict__ b_v0,
    const float* __restrict__ W_v1, const float* __restrict__ b_v1,
    const float* __restrict__ W_v2, const float* __restrict__ b_v2,
    const float* __restrict__ W_vs, const float* __restrict__ b_vs,
    float* __restrict__ out)
{
    __shared__ float sbase[8][NH];
    __shared__ float sv0[8][32];
    int t  = threadIdx.x;
    int r0 = blockIdx.x * 8;
    for (int idx = t; idx < 8 * NH; idx += 256)
        sbase[idx / NH][idx % NH] = g_base[(size_t)(r0 + idx / NH) * NH + (idx % NH)];
    __syncthreads();

    int w = t / 32, lane = t % 32;
    const float* bp = sbase[w];

    float acc = b_v0[lane];
    const float* wp = g_WTv0 + lane;
    #pragma unroll 8
    for (int k = 0; k < NH; k++) acc += wp[(size_t)k * 32] * bp[k];
    sv0[w][lane] = fmaxf(acc, 0.0f);
    __syncwarp();

    float acc1 = b_v1[lane];
    #pragma unroll
    for (int j = 0; j < 32; j++) acc1 += W_v1[lane * 32 + j] * sv0[w][j];
    acc1 = fmaxf(acc1, 0.0f);

    float part = W_v2[lane] * acc1;
    for (int k = lane; k < NH; k += 32) part += W_vs[k] * bp[k];
    #pragma unroll
    for (int off = 16; off > 0; off >>= 1)
        part += __shfl_down_sync(0xffffffffu, part, off);
    if (lane == 0) out[r0 + w] = part + b_v2[0] + b_vs[0];
}

// ---------------- action head: K=736 fp16 GEMM, 3-deep cp.async ring -------
// BM=BN=128, BK=32 halfs (64B rows), 256 threads = 8 warps (2x4), warp 64x32.
// smem pitch: 32 halfs + 8 pad = 80B -> conflict-free STS.128 & ldmatrix.
// Ring of 3 buffers, depth-2 prefetch, ONE __syncthreads per stage.
#define BUFB   (128 * 80)                  // bytes per (A or B) buffer
#define SM_ACT (3 * 2 * BUFB + 512)        // 3 bufs x (A+B) + bias

__global__ __launch_bounds__(256, 2) void act_kernel(
    const float* __restrict__ b_a1, const float* __restrict__ b_as,
    float* __restrict__ out)
{
    extern __shared__ __align__(16) char smem[];
    __half* sA   = (__half*)smem;                       // 3 x BUFB
    __half* sB   = (__half*)(smem + 3 * BUFB);          // 3 x BUFB
    float* sBias = (float*)(smem + 6 * BUFB);

    int t = threadIdx.x;
    int lane = t & 31, wid = t >> 5;
    int n0 = blockIdx.x * 128, m0 = blockIdx.y * 128;
    int mbase = (wid >> 2) * 64;
    int nbase = (wid & 3) * 32;
    if (t < 128) sBias[t] = b_a1[n0 + t] + b_as[n0 + t];

    uint32_t saB = (uint32_t)__cvta_generic_to_shared(sA);
    uint32_t sbB = (uint32_t)__cvta_generic_to_shared(sB);

    // loader: per stage each thread copies 2 A-chunks + 2 B-chunks of 16B
    int r0c = t >> 2, g0 = t & 3;          // rows 0..63, 16B group 0..3
    int r1c = r0c + 64;                    // rows 64..127
    const __half* gA0 = g_actA_h + (size_t)(m0 + r0c) * KP + g0 * 8;
    const __half* gA1 = g_actA_h + (size_t)(m0 + r1c) * KP + g0 * 8;
    const __half* gB0 = g_actB_h + (size_t)(n0 + r0c) * KP + g0 * 8;
    const __half* gB1 = g_actB_h + (size_t)(n0 + r1c) * KP + g0 * 8;
    uint32_t dA0 = saB + r0c * 80 + g0 * 16;
    uint32_t dA1 = saB + r1c * 80 + g0 * 16;
    uint32_t dB0 = sbB + r0c * 80 + g0 * 16;
    uint32_t dB1 = sbB + r1c * 80 + g0 * 16;

    // ldmatrix lane addressing (80B pitch, conflict-free)
    int l7 = lane & 7;
    int aRow = mbase + ((lane >> 3) & 1) * 8 + l7;
    int aK   = (lane >> 4) & 1;
    int bRow = ((lane >> 4) & 1) * 8 + l7;
    int bK   = (lane >> 3) & 1;
    uint32_t aAddr[4], bAddr[2];
    #pragma unroll
    for (int mt = 0; mt < 4; mt++) aAddr[mt] = saB + (aRow + mt * 16) * 80 + aK * 16;
    #pragma unroll
    for (int p = 0; p < 2; p++)    bAddr[p]  = sbB + (nbase + p * 16 + bRow) * 80 + bK * 16;

    float acc[4][4][4] = {};

    // prologue: stages 0,1 into buffers 0,1
    CP16(dA0, gA0); CP16(dA1, gA1); CP16(dB0, gB0); CP16(dB1, gB1);
    CPCOMMIT();
    {
        uint32_t bo = BUFB; int ko = 32;
        CP16(dA0 + bo, gA0 + ko); CP16(dA1 + bo, gA1 + ko);
        CP16(dB0 + bo, gB0 + ko); CP16(dB1 + bo, gB1 + ko);
        CPCOMMIT();
    }

    for (int s = 0; s < NSTG; s++) {
        if (s + 1 < NSTG) { CPWAIT(1); } else { CPWAIT(0); }
        __syncthreads();                    // stage s data visible; buf (s+2)%3 free

        if (s + 2 < NSTG) {                 // depth-2 prefetch into freed buffer
            uint32_t bo = ((s + 2) % 3) * BUFB;
            int ko = (s + 2) * 32;
            CP16(dA0 + bo, gA0 + ko); CP16(dA1 + bo, gA1 + ko);
            CP16(dB0 + bo, gB0 + ko); CP16(dB1 + bo, gB1 + ko);
            CPCOMMIT();
        }

        uint32_t bo = (s % 3) * BUFB;
        #pragma unroll
        for (int ks = 0; ks < 2; ks++) {
            uint32_t kb = bo + ks * 32;    // +16 halfs = 32B
            uint32_t afr[4][4];
            #pragma unroll
            for (int mt = 0; mt < 4; mt++) LDSM4(afr[mt], aAddr[mt] + kb);
            uint32_t bfr[4][2];
            #pragma unroll
            for (int p = 0; p < 2; p++) {
                uint32_t r[4];
                LDSM4(r, bAddr[p] + kb);
                bfr[2*p][0]   = r[0]; bfr[2*p][1]   = r[1];
                bfr[2*p+1][0] = r[2]; bfr[2*p+1][1] = r[3];
            }
            #pragma unroll
            for (int mt = 0; mt < 4; mt++)
                #pragma unroll
                for (int nt = 0; nt < 4; nt++) {
                    asm volatile(
                        "mma.sync.aligned.m16n8k16.row.col.f32.f16.f16.f32 "
                        "{%0,%1,%2,%3}, {%4,%5,%6,%7}, {%8,%9}, {%0,%1,%2,%3};\n"
                        : "+f"(acc[mt][nt][0]), "+f"(acc[mt][nt][1]),
                          "+f"(acc[mt][nt][2]), "+f"(acc[mt][nt][3])
                        : "r"(afr[mt][0]), "r"(afr[mt][1]),
                          "r"(afr[mt][2]), "r"(afr[mt][3]),
                          "r"(bfr[nt][0]), "r"(bfr[nt][1]));
                }
        }
    }

    // epilogue: bias + streaming store
    int r4 = lane >> 2, c4 = lane & 3;
    #pragma unroll
    for (int mt = 0; mt < 4; mt++) {
        int m = m0 + mbase + mt * 16 + r4;
        #pragma unroll
        for (int nt = 0; nt < 4; nt++) {
            int nl = nbase + nt * 8 + 2 * c4;
            float bi0 = sBias[nl], bi1 = sBias[nl + 1];
            float2 v0 = make_float2(acc[mt][nt][0] + bi0, acc[mt][nt][1] + bi1);
            float2 v1 = make_float2(acc[mt][nt][2] + bi0, acc[mt][nt][3] + bi1);
            __stcs((float2*)&out[NB + (size_t)m       * NMOVE + n0 + nl], v0);
            __stcs((float2*)&out[NB + (size_t)(m + 8) * NMOVE + n0 + nl], v1);
        }
    }
}

extern "C" void kernel_launch(void* const* d_in, const int* in_sizes, int n_in,
                              void* d_out, int out_size)
{
    const float* pov   = (const float*)d_in[0];
    const float* white = (const float*)d_in[1];
    const float* black = (const float*)d_in[2];
    const float* W_w   = (const float*)d_in[3];
    const float* b_w   = (const float*)d_in[4];
    const float* W_b   = (const float*)d_in[5];
    const float* b_b   = (const float*)d_in[6];
    const float* W_v0  = (const float*)d_in[7];
    const float* b_v0  = (const float*)d_in[8];
    const float* W_v1  = (const float*)d_in[9];
    const float* b_v1  = (const float*)d_in[10];
    const float* W_v2  = (const float*)d_in[11];
    const float* b_v2  = (const float*)d_in[12];
    const float* W_a0  = (const float*)d_in[13];
    const float* b_a0  = (const float*)d_in[14];
    const float* W_a1  = (const float*)d_in[15];
    const float* b_a1  = (const float*)d_in[16];
    const float* W_vs  = (const float*)d_in[17];
    const float* b_vs  = (const float*)d_in[18];
    const float* W_as  = (const float*)d_in[19];
    const float* b_as  = (const float*)d_in[20];
    float* out = (float*)d_out;

    cudaFuncSetAttribute(act_kernel,
                         cudaFuncAttributeMaxDynamicSharedMemorySize, SM_ACT);

    dim3 tb(32, 8);
    transpose_kernel<<<dim3(ND / 32, NBASE / 32), tb>>>(W_w, NBASE, ND, 0);
    transpose_kernel<<<dim3(ND / 32, NBASE / 32), tb>>>(W_b, NBASE, ND, 1);
    transpose_kernel<<<dim3(NH / 32, 1), tb>>>(W_v0, 32, NH, 2);
    bprep_kernel<<<NMOVE, 256>>>(W_a1, W_as);

    feature_kernel<<<NB * 2, NBASE>>>(pov, white, black, b_w, b_b);
    a0_kernel<<<dim3(NB / 64, NA0 / 48), 256>>>(W_a0, b_a0);
    value_kernel<<<NB / 8, 256>>>(b_v0, W_v1, b_v1, W_v2, b_v2, W_vs, b_vs, out);
    act_kernel<<<dim3(NMOVE / 128, NB / 128), 256, SM_ACT>>>(b_a1, b_as, out);
}

// round 7
// speedup vs baseline: 1.7935x; 1.0185x over previous
#include <cuda_runtime.h>
#include <cuda_fp16.h>
#include <cstdint>

#define NB    2048
#define ND    40960
#define NBASE 288
#define NH    576     // 2*NBASE
#define NA0   144
#define NMOVE 4096
#define KP    736     // padded act K: [a0(144) pad(16) base(576)]
#define AOFF  160     // base starts here
#define NSTG  23      // K chunks of 32 halfs (64B rows)

// -------- device scratch (no allocations allowed) --------
__device__ __half g_WTw_h[(size_t)ND * NBASE]; // W_w^T  [D, 288] fp16
__device__ __half g_WTb_h[(size_t)ND * NBASE]; // W_b^T  [D, 288] fp16
__device__ float  g_WTv0[NH * 32];             // W_v0^T [576, 32] fp32
__device__ float  g_base[(size_t)NB * NH];     // relu'd base, fp32
__device__ __half g_actA_h[(size_t)NB * KP];   // [relu(a0) | 0 | relu(base)] fp16
__device__ __half g_actB_h[(size_t)NMOVE * KP];// [W_a1 | 0 | W_as] fp16

#define CP16(dst, src) asm volatile("cp.async.cg.shared.global [%0], [%1], 16;" :: "r"(dst), "l"(src))
#define CPCOMMIT()     asm volatile("cp.async.commit_group;")
#define CPWAIT(n)      asm volatile("cp.async.wait_group %0;" :: "n"(n))
#define LDSM4(R, addr) asm volatile( \
    "ldmatrix.sync.aligned.m8n8.x4.shared.b16 {%0,%1,%2,%3}, [%4];" \
    : "=r"((R)[0]), "=r"((R)[1]), "=r"((R)[2]), "=r"((R)[3]) : "r"(addr))

// ---------------- transpose fp32 -> fp16: in[R,C] -> out[C,R] --------------
__global__ void transpose_h_kernel(const float* __restrict__ in, int R, int C, int which) {
    __half* out = (which == 0) ? g_WTw_h : g_WTb_h;
    __shared__ float tile[32][33];
    int c0 = blockIdx.x * 32;
    int r0 = blockIdx.y * 32;
    int x = threadIdx.x;
    #pragma unroll
    for (int yy = threadIdx.y; yy < 32; yy += 8) {
        int r = r0 + yy, c = c0 + x;
        tile[yy][x] = (r < R && c < C) ? in[(size_t)r * C + c] : 0.0f;
    }
    __syncthreads();
    #pragma unroll
    for (int yy = threadIdx.y; yy < 32; yy += 8) {
        int c = c0 + yy, r = r0 + x;
        if (r < R && c < C) out[(size_t)c * R + r] = __float2half(tile[x][yy]);
    }
}

// ---------------- transpose fp32 -> fp32 (W_v0 only) ----------------------
__global__ void transpose_kernel(const float* __restrict__ in, int R, int C) {
    float* out = g_WTv0;
    __shared__ float tile[32][33];
    int c0 = blockIdx.x * 32;
    int r0 = blockIdx.y * 32;
    int x = threadIdx.x;
    #pragma unroll
    for (int yy = threadIdx.y; yy < 32; yy += 8) {
        int r = r0 + yy, c = c0 + x;
        tile[yy][x] = (r < R && c < C) ? in[(size_t)r * C + c] : 0.0f;
    }
    __syncthreads();
    #pragma unroll
    for (int yy = threadIdx.y; yy < 32; yy += 8) {
        int c = c0 + yy, r = r0 + x;
        if (r < R && c < C) out[(size_t)c * R + r] = tile[x][yy];
    }
}

// ---------------- B-operand prep: g_actB_h = fp16([W_a1 | 0 | W_as]) -------
// Each thread handles 2 adjacent columns -> one aligned half2 store.
__global__ __launch_bounds__(256) void bprep_kernel(const float* __restrict__ W_a1,
                                                    const float* __restrict__ W_as) {
    int n = blockIdx.x;
    for (int c2 = threadIdx.x; c2 < KP / 2; c2 += 256) {
        int c = c2 * 2;
        float v0 = 0.0f, v1 = 0.0f;
        if (c < NA0) {
            const float2 w = *(const float2*)&W_a1[(size_t)n * NA0 + c];
            v0 = w.x; v1 = w.y;
        } else if (c >= AOFF) {
            const float2 w = *(const float2*)&W_as[(size_t)n * NH + (c - AOFF)];
            v0 = w.x; v1 = w.y;
        }
        *(__half2*)&g_actB_h[(size_t)n * KP + c] = __floats2half2_rn(v0, v1);
    }
}

// ---------------- feature transform + base ----------------
// One block per (batch row, color): grid = NB*2, 288 threads.
#define MAXNZ 512
__global__ __launch_bounds__(NBASE) void feature_kernel(
    const float* __restrict__ pov,
    const float* __restrict__ white,
    const float* __restrict__ black,
    const float* __restrict__ b_w,
    const float* __restrict__ b_b)
{
    __shared__ int   s_idx[MAXNZ];
    __shared__ float s_val[MAXNZ];
    __shared__ int   s_cnt;
    int b = blockIdx.x >> 1;
    int h = blockIdx.x & 1;       // 0 = white, 1 = black
    int i = threadIdx.x;
    if (i == 0) s_cnt = 0;
    if (h == 0 && i < 16) g_actA_h[(size_t)b * KP + NA0 + i] = __float2half(0.0f);
    __syncthreads();

    const float* src = h ? black : white;
    const float4* row = reinterpret_cast<const float4*>(src + (size_t)b * ND);
    // 2-wide unrolled scan: two independent streaming loads in flight.
    for (int u = i; u < ND / 4; u += 2 * NBASE) {
        float4 v0 = __ldcs(&row[u]);
        int u1 = u + NBASE;
        bool has1 = (u1 < ND / 4);
        float4 v1 = has1 ? __ldcs(&row[u1]) : make_float4(0.f, 0.f, 0.f, 0.f);
        if (v0.x != 0.0f) { int p = atomicAdd(&s_cnt, 1); if (p < MAXNZ) { s_idx[p] = 4*u+0; s_val[p] = v0.x; } }
        if (v0.y != 0.0f) { int p = atomicAdd(&s_cnt, 1); if (p < MAXNZ) { s_idx[p] = 4*u+1; s_val[p] = v0.y; } }
        if (v0.z != 0.0f) { int p = atomicAdd(&s_cnt, 1); if (p < MAXNZ) { s_idx[p] = 4*u+2; s_val[p] = v0.z; } }
        if (v0.w != 0.0f) { int p = atomicAdd(&s_cnt, 1); if (p < MAXNZ) { s_idx[p] = 4*u+3; s_val[p] = v0.w; } }
        if (has1) {
            if (v1.x != 0.0f) { int p = atomicAdd(&s_cnt, 1); if (p < MAXNZ) { s_idx[p] = 4*u1+0; s_val[p] = v1.x; } }
            if (v1.y != 0.0f) { int p = atomicAdd(&s_cnt, 1); if (p < MAXNZ) { s_idx[p] = 4*u1+1; s_val[p] = v1.y; } }
            if (v1.z != 0.0f) { int p = atomicAdd(&s_cnt, 1); if (p < MAXNZ) { s_idx[p] = 4*u1+2; s_val[p] = v1.z; } }
            if (v1.w != 0.0f) { int p = atomicAdd(&s_cnt, 1); if (p < MAXNZ) { s_idx[p] = 4*u1+3; s_val[p] = v1.w; } }
        }
    }
    __syncthreads();

    const __half* WT = h ? g_WTb_h : g_WTw_h;
    float acc = h ? b_b[i] : b_w[i];
    int n = s_cnt;
    if (n > MAXNZ) n = MAXNZ;
    int k = 0;
    for (; k + 4 <= n; k += 4) {
        float p0 = s_val[k+0] * __half2float(WT[(size_t)s_idx[k+0] * NBASE + i]);
        float p1 = s_val[k+1] * __half2float(WT[(size_t)s_idx[k+1] * NBASE + i]);
        float p2 = s_val[k+2] * __half2float(WT[(size_t)s_idx[k+2] * NBASE + i]);
        float p3 = s_val[k+3] * __half2float(WT[(size_t)s_idx[k+3] * NBASE + i]);
        acc += (p0 + p1) + (p2 + p3);
    }
    for (; k < n; k++)
        acc += s_val[k] * __half2float(WT[(size_t)s_idx[k] * NBASE + i]);

    float pv = pov[b];
    int pos;
    if (h == 0) pos = (pv > 0.5f) ? i : (NBASE + i);
    else        pos = (pv > 0.5f) ? (NBASE + i) : i;
    float r = fmaxf(acc, 0.0f);
    g_base[(size_t)b * NH + pos] = r;
    g_actA_h[(size_t)b * KP + AOFF + pos] = __float2half(r);
}

// ---------------- a0 = relu(base @ W_a0^T + b_a0) -> fp16 ------------------
__global__ __launch_bounds__(256) void a0_kernel(const float* __restrict__ W_a0,
                                                 const float* __restrict__ b_a0)
{
    __shared__ float sA[16][64];
    __shared__ float sB[16][48];
    int m0 = blockIdx.x * 64;
    int n0 = blockIdx.y * 48;
    int t  = threadIdx.x;
    int tx = t % 16, ty = t / 16;
    float acc[4][3] = {};
    int am = t >> 2, ak = (t & 3) * 4;

    for (int kt = 0; kt < NH; kt += 16) {
        float4 av = *reinterpret_cast<const float4*>(&g_base[(size_t)(m0 + am) * NH + kt + ak]);
        float4 bv = make_float4(0.f, 0.f, 0.f, 0.f);
        if (t < 192) bv = *reinterpret_cast<const float4*>(&W_a0[(size_t)(n0 + am) * NH + kt + ak]);
        __syncthreads();
        sA[ak+0][am] = av.x; sA[ak+1][am] = av.y; sA[ak+2][am] = av.z; sA[ak+3][am] = av.w;
        if (t < 192) { sB[ak+0][am] = bv.x; sB[ak+1][am] = bv.y; sB[ak+2][am] = bv.z; sB[ak+3][am] = bv.w; }
        __syncthreads();
        #pragma unroll
        for (int k = 0; k < 16; k++) {
            float a[4], bb[3];
            #pragma unroll
            for (int ii = 0; ii < 4; ii++) a[ii] = sA[k][ty*4 + ii];
            #pragma unroll
            for (int j = 0; j < 3; j++)  bb[j] = sB[k][tx*3 + j];
            #pragma unroll
            for (int ii = 0; ii < 4; ii++)
                #pragma unroll
                for (int j = 0; j < 3; j++)
                    acc[ii][j] += a[ii] * bb[j];
        }
    }
    #pragma unroll
    for (int ii = 0; ii < 4; ii++) {
        int m = m0 + ty*4 + ii;
        #pragma unroll
        for (int j = 0; j < 3; j++) {
            int n = n0 + tx*3 + j;
            g_actA_h[(size_t)m * KP + n] = __float2half(fmaxf(acc[ii][j] + b_a0[n], 0.0f));
        }
    }
}

// ---------------- value head (fp32) ----------------
__global__ __launch_bounds__(256) void value_kernel(
    const float* __restrict__ b_v0,
    const float* __restrict__ W_v1, const float* __restrict__ b_v1,
    const float* __restrict__ W_v2, const float* __restrict__ b_v2,
    const float* __restrict__ W_vs, const float* __restrict__ b_vs,
    float* __restrict__ out)
{
    __shared__ float sbase[8][NH];
    __shared__ float sv0[8][32];
    int t  = threadIdx.x;
    int r0 = blockIdx.x * 8;
    for (int idx = t; idx < 8 * NH; idx += 256)
        sbase[idx / NH][idx % NH] = g_base[(size_t)(r0 + idx / NH) * NH + (idx % NH)];
    __syncthreads();

    int w = t / 32, lane = t % 32;
    const float* bp = sbase[w];

    float acc = b_v0[lane];
    const float* wp = g_WTv0 + lane;
    #pragma unroll 8
    for (int k = 0; k < NH; k++) acc += wp[(size_t)k * 32] * bp[k];
    sv0[w][lane] = fmaxf(acc, 0.0f);
    __syncwarp();

    float acc1 = b_v1[lane];
    #pragma unroll
    for (int j = 0; j < 32; j++) acc1 += W_v1[lane * 32 + j] * sv0[w][j];
    acc1 = fmaxf(acc1, 0.0f);

    float part = W_v2[lane] * acc1;
    for (int k = lane; k < NH; k += 32) part += W_vs[k] * bp[k];
    #pragma unroll
    for (int off = 16; off > 0; off >>= 1)
        part += __shfl_down_sync(0xffffffffu, part, off);
    if (lane == 0) out[r0 + w] = part + b_v2[0] + b_vs[0];
}

// ---------------- action head: K=736 fp16 GEMM, 4-deep cp.async ring -------
// BM=BN=128, BK=32 halfs (64B rows), 256 threads = 8 warps (2x4), warp 64x32.
// smem pitch: 32 halfs + 8 pad = 80B -> conflict-free STS.128 & ldmatrix.
#define BUFB   (128 * 80)                  // bytes per (A or B) buffer
#define NRING  4
#define SM_ACT (NRING * 2 * BUFB + 512)    // 4 bufs x (A+B) + bias = 82432

__global__ __launch_bounds__(256, 2) void act_kernel(
    const float* __restrict__ b_a1, const float* __restrict__ b_as,
    float* __restrict__ out)
{
    extern __shared__ __align__(16) char smem[];
    __half* sA   = (__half*)smem;                        // NRING x BUFB
    __half* sB   = (__half*)(smem + NRING * BUFB);       // NRING x BUFB
    float* sBias = (float*)(smem + 2 * NRING * BUFB);

    int t = threadIdx.x;
    int lane = t & 31, wid = t >> 5;
    int n0 = blockIdx.x * 128, m0 = blockIdx.y * 128;
    int mbase = (wid >> 2) * 64;
    int nbase = (wid & 3) * 32;
    if (t < 128) sBias[t] = b_a1[n0 + t] + b_as[n0 + t];

    uint32_t saB = (uint32_t)__cvta_generic_to_shared(sA);
    uint32_t sbB = (uint32_t)__cvta_generic_to_shared(sB);

    // loader: per stage each thread copies 2 A-chunks + 2 B-chunks of 16B
    int r0c = t >> 2, g0 = t & 3;
    int r1c = r0c + 64;
    const __half* gA0 = g_actA_h + (size_t)(m0 + r0c) * KP + g0 * 8;
    const __half* gA1 = g_actA_h + (size_t)(m0 + r1c) * KP + g0 * 8;
    const __half* gB0 = g_actB_h + (size_t)(n0 + r0c) * KP + g0 * 8;
    const __half* gB1 = g_actB_h + (size_t)(n0 + r1c) * KP + g0 * 8;
    uint32_t dA0 = saB + r0c * 80 + g0 * 16;
    uint32_t dA1 = saB + r1c * 80 + g0 * 16;
    uint32_t dB0 = sbB + r0c * 80 + g0 * 16;
    uint32_t dB1 = sbB + r1c * 80 + g0 * 16;

    // ldmatrix lane addressing (80B pitch, conflict-free)
    int l7 = lane & 7;
    int aRow = mbase + ((lane >> 3) & 1) * 8 + l7;
    int aK   = (lane >> 4) & 1;
    int bRow = ((lane >> 4) & 1) * 8 + l7;
    int bK   = (lane >> 3) & 1;
    uint32_t aAddr[4], bAddr[2];
    #pragma unroll
    for (int mt = 0; mt < 4; mt++) aAddr[mt] = saB + (aRow + mt * 16) * 80 + aK * 16;
    #pragma unroll
    for (int p = 0; p < 2; p++)    bAddr[p]  = sbB + (nbase + p * 16 + bRow) * 80 + bK * 16;

    float acc[4][4][4] = {};

    // prologue: stages 0,1,2 into buffers 0,1,2
    #pragma unroll
    for (int s = 0; s < 3; s++) {
        uint32_t bo = s * BUFB; int ko = s * 32;
        CP16(dA0 + bo, gA0 + ko); CP16(dA1 + bo, gA1 + ko);
        CP16(dB0 + bo, gB0 + ko); CP16(dB1 + bo, gB1 + ko);
        CPCOMMIT();
    }

    for (int s = 0; s < NSTG; s++) {
        // exact tail waits: pending groups = min(3, NSTG - s)
        if (s + 3 <= NSTG)      { CPWAIT(2); }
        else if (s + 2 == NSTG) { CPWAIT(1); }
        else                    { CPWAIT(0); }
        __syncthreads();                    // stage s visible; buf (s+3)%NRING free

        if (s + 3 < NSTG) {                 // depth-3 prefetch
            uint32_t bo = ((s + 3) % NRING) * BUFB;
            int ko = (s + 3) * 32;
            CP16(dA0 + bo, gA0 + ko); CP16(dA1 + bo, gA1 + ko);
            CP16(dB0 + bo, gB0 + ko); CP16(dB1 + bo, gB1 + ko);
            CPCOMMIT();
        }

        uint32_t bo = (s % NRING) * BUFB;
        #pragma unroll
        for (int ks = 0; ks < 2; ks++) {
            uint32_t kb = bo + ks * 32;
            uint32_t afr[4][4];
            #pragma unroll
            for (int mt = 0; mt < 4; mt++) LDSM4(afr[mt], aAddr[mt] + kb);
            uint32_t bfr[4][2];
            #pragma unroll
            for (int p = 0; p < 2; p++) {
                uint32_t r[4];
                LDSM4(r, bAddr[p] + kb);
                bfr[2*p][0]   = r[0]; bfr[2*p][1]   = r[1];
                bfr[2*p+1][0] = r[2]; bfr[2*p+1][1] = r[3];
            }
            #pragma unroll
            for (int mt = 0; mt < 4; mt++)
                #pragma unroll
                for (int nt = 0; nt < 4; nt++) {
                    asm volatile(
                        "mma.sync.aligned.m16n8k16.row.col.f32.f16.f16.f32 "
                        "{%0,%1,%2,%3}, {%4,%5,%6,%7}, {%8,%9}, {%0,%1,%2,%3};\n"
                        : "+f"(acc[mt][nt][0]), "+f"(acc[mt][nt][1]),
                          "+f"(acc[mt][nt][2]), "+f"(acc[mt][nt][3])
                        : "r"(afr[mt][0]), "r"(afr[mt][1]),
                          "r"(afr[mt][2]), "r"(afr[mt][3]),
                          "r"(bfr[nt][0]), "r"(bfr[nt][1]));
                }
        }
    }

    // epilogue: bias + streaming store
    int r4 = lane >> 2, c4 = lane & 3;
    #pragma unroll
    for (int mt = 0; mt < 4; mt++) {
        int m = m0 + mbase + mt * 16 + r4;
        #pragma unroll
        for (int nt = 0; nt < 4; nt++) {
            int nl = nbase + nt * 8 + 2 * c4;
            float bi0 = sBias[nl], bi1 = sBias[nl + 1];
            float2 v0 = make_float2(acc[mt][nt][0] + bi0, acc[mt][nt][1] + bi1);
            float2 v1 = make_float2(acc[mt][nt][2] + bi0, acc[mt][nt][3] + bi1);
            __stcs((float2*)&out[NB + (size_t)m       * NMOVE + n0 + nl], v0);
            __stcs((float2*)&out[NB + (size_t)(m + 8) * NMOVE + n0 + nl], v1);
        }
    }
}

extern "C" void kernel_launch(void* const* d_in, const int* in_sizes, int n_in,
                              void* d_out, int out_size)
{
    const float* pov   = (const float*)d_in[0];
    const float* white = (const float*)d_in[1];
    const float* black = (const float*)d_in[2];
    const float* W_w   = (const float*)d_in[3];
    const float* b_w   = (const float*)d_in[4];
    const float* W_b   = (const float*)d_in[5];
    const float* b_b   = (const float*)d_in[6];
    const float* W_v0  = (const float*)d_in[7];
    const float* b_v0  = (const float*)d_in[8];
    const float* W_v1  = (const float*)d_in[9];
    const float* b_v1  = (const float*)d_in[10];
    const float* W_v2  = (const float*)d_in[11];
    const float* b_v2  = (const float*)d_in[12];
    const float* W_a0  = (const float*)d_in[13];
    const float* b_a0  = (const float*)d_in[14];
    const float* W_a1  = (const float*)d_in[15];
    const float* b_a1  = (const float*)d_in[16];
    const float* W_vs  = (const float*)d_in[17];
    const float* b_vs  = (const float*)d_in[18];
    const float* W_as  = (const float*)d_in[19];
    const float* b_as  = (const float*)d_in[20];
    float* out = (float*)d_out;

    cudaFuncSetAttribute(act_kernel,
                         cudaFuncAttributeMaxDynamicSharedMemorySize, SM_ACT);

    dim3 tb(32, 8);
    transpose_h_kernel<<<dim3(ND / 32, NBASE / 32), tb>>>(W_w, NBASE, ND, 0);
    transpose_h_kernel<<<dim3(ND / 32, NBASE / 32), tb>>>(W_b, NBASE, ND, 1);
    transpose_kernel<<<dim3(NH / 32, 1), tb>>>(W_v0, 32, NH);
    bprep_kernel<<<NMOVE, 256>>>(W_a1, W_as);

    feature_kernel<<<NB * 2, NBASE>>>(pov, white, black, b_w, b_b);
    a0_kernel<<<dim3(NB / 64, NA0 / 48), 256>>>(W_a0, b_a0);
    value_kernel<<<NB / 8, 256>>>(b_v0, W_v1, b_v1, W_v2, b_v2, W_vs, b_vs, out);
    act_kernel<<<dim3(NMOVE / 128, NB / 128), 256, SM_ACT>>>(b_a1, b_as, out);
}